// round 8
// baseline (speedup 1.0000x reference)
#include <cuda_runtime.h>

#define HID 100
#define T   10
#define NB  5
#define G3  300
#define BT  128           // batch tile per CTA
#define BG  16            // batch groups
#define RB  8             // batch elems per thread
#define NTH 800           // 50 jp-lanes * 16 batch-groups
#define B_MAX 65536

// SMEM float offsets
#define OFF_W 0           // 30000 floats : W6 [k=100][jp=50][6] = r0,z0,n0,r1,z1,n1
#define OFF_H 30000       // 12800 floats : h [k=100][128]
#define OFF_A 42800       // 1024 floats  : aux
#define SMEM_FLOATS 43824 // 175296 bytes

// Scratch (static device memory; kernel_launch stays allocation-free)
__device__ float g_VBUF[(T + NB) * B_MAX];   // sliding input window [slot][b]
__device__ float g_H1[T * HID * B_MAX];      // layer0 outputs [t][j][b]
__device__ float g_GI1[T * G3 * B_MAX];      // layer1 input gates [t][g][b]

__device__ __forceinline__ float sigf(float x)   { return 1.f / (1.f + __expf(-x)); }
__device__ __forceinline__ float tanhf_(float x) { return 1.f - 2.f / (__expf(2.f * x) + 1.f); }

// ---- packed fp32x2 helpers ----
#define PACK2(d, s) asm("mov.b64 %0, {%1, %1};" : "=l"(d) : "f"(s))
#define FMA2(acc, a, b) asm("fma.rn.f32x2 %0, %1, %2, %0;" : "+l"(acc) : "l"(a), "l"(b))
#define UNPACK2(lo, hi, v) asm("mov.b64 {%0, %1}, %2;" : "=f"(lo), "=f"(hi) : "l"(v))

// Accumulator index: [j(2)][gate(3)][q(4)] ; q: 0={4bg,4bg+1} 1={4bg+2,4bg+3}
//                                            2={64+4bg,+1}  3={64+4bg+2,+3}
#define AIX(j, g, q) ((j) * 12 + (g) * 4 + (q))

// Per thread-k: 3 LDS.64 (w6) + 2 LDS.128 (h) + 6 PACK2 + 24 FFMA2 = 48 MACs
__device__ __forceinline__ void matvec_jp(const float* __restrict__ WtS,
                                          const float* __restrict__ hS,
                                          int jp, int bg,
                                          unsigned long long acc[24])
{
    #pragma unroll
    for (int i = 0; i < 24; ++i) acc[i] = 0ull;
    const float2* __restrict__ wb = (const float2*)(WtS + jp * 6);
    const float*  __restrict__ hb = hS + 4 * bg;
    #pragma unroll 5
    for (int k = 0; k < HID; ++k) {
        float2 w01 = wb[k * 150 + 0];   // r0, z0
        float2 w23 = wb[k * 150 + 1];   // n0, r1
        float2 w45 = wb[k * 150 + 2];   // z1, n1
        unsigned long long wr0, wz0, wn0, wr1, wz1, wn1;
        PACK2(wr0, w01.x); PACK2(wz0, w01.y); PACK2(wn0, w23.x);
        PACK2(wr1, w23.y); PACK2(wz1, w45.x); PACK2(wn1, w45.y);
        ulonglong2 hl = *(const ulonglong2*)(hb + k * BT);        // b: 4bg..4bg+3
        ulonglong2 hh = *(const ulonglong2*)(hb + k * BT + 64);   // b: 64+4bg..+3
        FMA2(acc[AIX(0,0,0)], hl.x, wr0); FMA2(acc[AIX(0,0,1)], hl.y, wr0);
        FMA2(acc[AIX(0,0,2)], hh.x, wr0); FMA2(acc[AIX(0,0,3)], hh.y, wr0);
        FMA2(acc[AIX(0,1,0)], hl.x, wz0); FMA2(acc[AIX(0,1,1)], hl.y, wz0);
        FMA2(acc[AIX(0,1,2)], hh.x, wz0); FMA2(acc[AIX(0,1,3)], hh.y, wz0);
        FMA2(acc[AIX(0,2,0)], hl.x, wn0); FMA2(acc[AIX(0,2,1)], hl.y, wn0);
        FMA2(acc[AIX(0,2,2)], hh.x, wn0); FMA2(acc[AIX(0,2,3)], hh.y, wn0);
        FMA2(acc[AIX(1,0,0)], hl.x, wr1); FMA2(acc[AIX(1,0,1)], hl.y, wr1);
        FMA2(acc[AIX(1,0,2)], hh.x, wr1); FMA2(acc[AIX(1,0,3)], hh.y, wr1);
        FMA2(acc[AIX(1,1,0)], hl.x, wz1); FMA2(acc[AIX(1,1,1)], hl.y, wz1);
        FMA2(acc[AIX(1,1,2)], hh.x, wz1); FMA2(acc[AIX(1,1,3)], hh.y, wz1);
        FMA2(acc[AIX(1,2,0)], hl.x, wn1); FMA2(acc[AIX(1,2,1)], hl.y, wn1);
        FMA2(acc[AIX(1,2,2)], hh.x, wn1); FMA2(acc[AIX(1,2,3)], hh.y, wn1);
    }
}

// Global W [g=300][k=100] -> smem W6 [k][jp][6], slot = (j&1)*3 + gate
__device__ __forceinline__ void load_weight6(const float* __restrict__ W,
                                             float* __restrict__ WtS, int tid)
{
    for (int idx = tid; idx < G3 * HID; idx += NTH) {
        int g = idx / HID;
        int k = idx - g * HID;
        int gate = g / HID;
        int j    = g - gate * HID;
        WtS[k * G3 + (j >> 1) * 6 + (j & 1) * 3 + gate] = W[idx];
    }
}

__device__ __forceinline__ float gru_cell(float gi_r, float gi_z, float gi_n,
                                          float gr, float gz, float gn, float hold)
{
    float r = sigf(gi_r + gr);
    float z = sigf(gi_z + gz);
    float n = tanhf_(gi_n + r * gn);
    return (1.f - z) * n + z * hold;
}

// unpack one j's 12 accumulators into 8 floats per gate
#define UNPACK_J(jj, R, Z, N, acc) \
    UNPACK2(R[0], R[1], acc[AIX(jj,0,0)]); UNPACK2(R[2], R[3], acc[AIX(jj,0,1)]); \
    UNPACK2(R[4], R[5], acc[AIX(jj,0,2)]); UNPACK2(R[6], R[7], acc[AIX(jj,0,3)]); \
    UNPACK2(Z[0], Z[1], acc[AIX(jj,1,0)]); UNPACK2(Z[2], Z[3], acc[AIX(jj,1,1)]); \
    UNPACK2(Z[4], Z[5], acc[AIX(jj,1,2)]); UNPACK2(Z[6], Z[7], acc[AIX(jj,1,3)]); \
    UNPACK2(N[0], N[1], acc[AIX(jj,2,0)]); UNPACK2(N[2], N[3], acc[AIX(jj,2,1)]); \
    UNPACK2(N[4], N[5], acc[AIX(jj,2,2)]); UNPACK2(N[6], N[7], acc[AIX(jj,2,3)])

// ---------------- init: VBUF[s][b] = x[b][s] ----------------
__global__ void k_init(const float* __restrict__ x, int B)
{
    int idx = blockIdx.x * blockDim.x + threadIdx.x;
    if (idx < B * T) {
        int b = idx / T, s = idx - b * T;
        g_VBUF[s * B + b] = x[idx];
    }
}

// ---------------- K1: layer-0 recurrence ----------------
__global__ void __launch_bounds__(NTH, 1)
k_layer0(const float* __restrict__ Whh0, const float* __restrict__ Wih0,
         const float* __restrict__ bih0, const float* __restrict__ bhh0,
         int iter, int B)
{
    extern __shared__ float sm[];
    float* WtS  = sm + OFF_W;
    float* hS   = sm + OFF_H;
    float* auxS = sm + OFF_A;   // [0:300) wih, [304:604) bih, [608:908) bhh

    const int tid = threadIdx.x;
    const int jp  = tid >> 4;
    const int bg  = tid & 15;
    const int bg0 = blockIdx.x * BT;
    const int j0  = 2 * jp, j1 = 2 * jp + 1;

    load_weight6(Whh0, WtS, tid);
    for (int idx = tid; idx < G3; idx += NTH) {
        auxS[idx]       = Wih0[idx];
        auxS[304 + idx] = bih0[idx];
        auxS[608 + idx] = bhh0[idx];
    }
    for (int idx = tid; idx < HID * BT; idx += NTH) hS[idx] = 0.f;
    __syncthreads();

    for (int t = 0; t < T; ++t) {
        unsigned long long acc[24];
        matvec_jp(WtS, hS, jp, bg, acc);

        const float* xb = g_VBUF + (size_t)(iter + t) * B + bg0 + 4 * bg;
        float xv[8];
        *(float4*)(xv)     = *(const float4*)xb;
        *(float4*)(xv + 4) = *(const float4*)(xb + 64);

        float hn0[8], hn1[8];
        {   // j = j0
            float R[8], Z[8], N[8], ho[8];
            UNPACK_J(0, R, Z, N, acc);
            *(float4*)(ho)     = *(const float4*)(hS + j0 * BT + 4 * bg);
            *(float4*)(ho + 4) = *(const float4*)(hS + j0 * BT + 64 + 4 * bg);
            const float wir = auxS[j0],       wiz = auxS[100 + j0], win = auxS[200 + j0];
            const float bir = auxS[304 + j0], biz = auxS[404 + j0], bin = auxS[504 + j0];
            const float bhr = auxS[608 + j0], bhz = auxS[708 + j0], bhn = auxS[808 + j0];
            #pragma unroll
            for (int i = 0; i < 8; ++i)
                hn0[i] = gru_cell(xv[i]*wir + bir, xv[i]*wiz + biz, xv[i]*win + bin,
                                  R[i] + bhr, Z[i] + bhz, N[i] + bhn, ho[i]);
        }
        {   // j = j1
            float R[8], Z[8], N[8], ho[8];
            UNPACK_J(1, R, Z, N, acc);
            *(float4*)(ho)     = *(const float4*)(hS + j1 * BT + 4 * bg);
            *(float4*)(ho + 4) = *(const float4*)(hS + j1 * BT + 64 + 4 * bg);
            const float wir = auxS[j1],       wiz = auxS[100 + j1], win = auxS[200 + j1];
            const float bir = auxS[304 + j1], biz = auxS[404 + j1], bin = auxS[504 + j1];
            const float bhr = auxS[608 + j1], bhz = auxS[708 + j1], bhn = auxS[808 + j1];
            #pragma unroll
            for (int i = 0; i < 8; ++i)
                hn1[i] = gru_cell(xv[i]*wir + bir, xv[i]*wiz + biz, xv[i]*win + bin,
                                  R[i] + bhr, Z[i] + bhz, N[i] + bhn, ho[i]);
        }

        __syncthreads();   // all matvec/h_old reads of hS complete
        *(float4*)(hS + j0 * BT + 4 * bg)      = *(float4*)(hn0);
        *(float4*)(hS + j0 * BT + 64 + 4 * bg) = *(float4*)(hn0 + 4);
        *(float4*)(hS + j1 * BT + 4 * bg)      = *(float4*)(hn1);
        *(float4*)(hS + j1 * BT + 64 + 4 * bg) = *(float4*)(hn1 + 4);
        float* gw0 = g_H1 + (size_t)(t * HID + j0) * B + bg0 + 4 * bg;
        float* gw1 = g_H1 + (size_t)(t * HID + j1) * B + bg0 + 4 * bg;
        *(float4*)(gw0)      = *(float4*)(hn0);
        *(float4*)(gw0 + 64) = *(float4*)(hn0 + 4);
        *(float4*)(gw1)      = *(float4*)(hn1);
        *(float4*)(gw1 + 64) = *(float4*)(hn1 + 4);
        __syncthreads();
    }
}

// ---------------- K2: GI1[t] = Wih1 * H1[t] + b_ih1 (loops all t) ----------------
__global__ void __launch_bounds__(NTH, 1)
k_gi1(const float* __restrict__ Wih1, const float* __restrict__ bih1, int B)
{
    extern __shared__ float sm[];
    float* WtS  = sm + OFF_W;
    float* hS   = sm + OFF_H;
    float* auxS = sm + OFF_A;

    const int tid = threadIdx.x;
    const int jp  = tid >> 4;
    const int bg  = tid & 15;
    const int bg0 = blockIdx.x * BT;
    const int j0  = 2 * jp, j1 = 2 * jp + 1;

    load_weight6(Wih1, WtS, tid);
    for (int idx = tid; idx < G3; idx += NTH) auxS[idx] = bih1[idx];
    __syncthreads();

    for (int t = 0; t < T; ++t) {
        // stage H1[t]
        for (int idx = tid * 4; idx < HID * BT; idx += NTH * 4)
            *(float4*)(hS + idx) = *(const float4*)(g_H1 + (size_t)t * HID * B
                                      + (size_t)(idx >> 7) * B + bg0 + (idx & 127));
        __syncthreads();

        unsigned long long acc[24];
        matvec_jp(WtS, hS, jp, bg, acc);

        float R[8], Z[8], N[8];
        float* gbase = g_GI1 + (size_t)t * G3 * B + bg0 + 4 * bg;
        {   const float br = auxS[j0], bz = auxS[100 + j0], bn = auxS[200 + j0];
            UNPACK_J(0, R, Z, N, acc);
            float* p = gbase + (size_t)j0 * B;
            *(float4*)(p)      = make_float4(R[0]+br, R[1]+br, R[2]+br, R[3]+br);
            *(float4*)(p + 64) = make_float4(R[4]+br, R[5]+br, R[6]+br, R[7]+br);
            p = gbase + (size_t)(100 + j0) * B;
            *(float4*)(p)      = make_float4(Z[0]+bz, Z[1]+bz, Z[2]+bz, Z[3]+bz);
            *(float4*)(p + 64) = make_float4(Z[4]+bz, Z[5]+bz, Z[6]+bz, Z[7]+bz);
            p = gbase + (size_t)(200 + j0) * B;
            *(float4*)(p)      = make_float4(N[0]+bn, N[1]+bn, N[2]+bn, N[3]+bn);
            *(float4*)(p + 64) = make_float4(N[4]+bn, N[5]+bn, N[6]+bn, N[7]+bn); }
        {   const float br = auxS[j1], bz = auxS[100 + j1], bn = auxS[200 + j1];
            UNPACK_J(1, R, Z, N, acc);
            float* p = gbase + (size_t)j1 * B;
            *(float4*)(p)      = make_float4(R[0]+br, R[1]+br, R[2]+br, R[3]+br);
            *(float4*)(p + 64) = make_float4(R[4]+br, R[5]+br, R[6]+br, R[7]+br);
            p = gbase + (size_t)(100 + j1) * B;
            *(float4*)(p)      = make_float4(Z[0]+bz, Z[1]+bz, Z[2]+bz, Z[3]+bz);
            *(float4*)(p + 64) = make_float4(Z[4]+bz, Z[5]+bz, Z[6]+bz, Z[7]+bz);
            p = gbase + (size_t)(200 + j1) * B;
            *(float4*)(p)      = make_float4(N[0]+bn, N[1]+bn, N[2]+bn, N[3]+bn);
            *(float4*)(p + 64) = make_float4(N[4]+bn, N[5]+bn, N[6]+bn, N[7]+bn); }
        __syncthreads();
    }
}

// ---------------- K3: layer-1 recurrence + final linear ----------------
__global__ void __launch_bounds__(NTH, 1)
k_layer1(const float* __restrict__ Whh1, const float* __restrict__ bhh1,
         const float* __restrict__ Wlin, const float* __restrict__ blin,
         float* __restrict__ out, int iter, int B)
{
    extern __shared__ float sm[];
    float* WtS  = sm + OFF_W;
    float* hS   = sm + OFF_H;
    float* auxS = sm + OFF_A;   // [0:300) bhh, [304:404) wlin

    const int tid = threadIdx.x;
    const int jp  = tid >> 4;
    const int bg  = tid & 15;
    const int bg0 = blockIdx.x * BT;
    const int j0  = 2 * jp, j1 = 2 * jp + 1;

    load_weight6(Whh1, WtS, tid);
    for (int idx = tid; idx < G3; idx += NTH) auxS[idx] = bhh1[idx];
    for (int idx = tid; idx < HID; idx += NTH) auxS[304 + idx] = Wlin[idx];
    for (int idx = tid; idx < HID * BT; idx += NTH) hS[idx] = 0.f;
    __syncthreads();

    for (int t = 0; t < T; ++t) {
        unsigned long long acc[24];
        matvec_jp(WtS, hS, jp, bg, acc);

        const float* gbase = g_GI1 + (size_t)t * G3 * B + bg0 + 4 * bg;
        float hn0[8], hn1[8];
        {   // j = j0
            float R[8], Z[8], N[8], ho[8], gr[8], gz[8], gn[8];
            UNPACK_J(0, R, Z, N, acc);
            *(float4*)(gr)     = *(const float4*)(gbase + (size_t)j0 * B);
            *(float4*)(gr + 4) = *(const float4*)(gbase + (size_t)j0 * B + 64);
            *(float4*)(gz)     = *(const float4*)(gbase + (size_t)(100 + j0) * B);
            *(float4*)(gz + 4) = *(const float4*)(gbase + (size_t)(100 + j0) * B + 64);
            *(float4*)(gn)     = *(const float4*)(gbase + (size_t)(200 + j0) * B);
            *(float4*)(gn + 4) = *(const float4*)(gbase + (size_t)(200 + j0) * B + 64);
            *(float4*)(ho)     = *(const float4*)(hS + j0 * BT + 4 * bg);
            *(float4*)(ho + 4) = *(const float4*)(hS + j0 * BT + 64 + 4 * bg);
            const float bhr = auxS[j0], bhz = auxS[100 + j0], bhn = auxS[200 + j0];
            #pragma unroll
            for (int i = 0; i < 8; ++i)
                hn0[i] = gru_cell(gr[i], gz[i], gn[i],
                                  R[i] + bhr, Z[i] + bhz, N[i] + bhn, ho[i]);
        }
        {   // j = j1
            float R[8], Z[8], N[8], ho[8], gr[8], gz[8], gn[8];
            UNPACK_J(1, R, Z, N, acc);
            *(float4*)(gr)     = *(const float4*)(gbase + (size_t)j1 * B);
            *(float4*)(gr + 4) = *(const float4*)(gbase + (size_t)j1 * B + 64);
            *(float4*)(gz)     = *(const float4*)(gbase + (size_t)(100 + j1) * B);
            *(float4*)(gz + 4) = *(const float4*)(gbase + (size_t)(100 + j1) * B + 64);
            *(float4*)(gn)     = *(const float4*)(gbase + (size_t)(200 + j1) * B);
            *(float4*)(gn + 4) = *(const float4*)(gbase + (size_t)(200 + j1) * B + 64);
            *(float4*)(ho)     = *(const float4*)(hS + j1 * BT + 4 * bg);
            *(float4*)(ho + 4) = *(const float4*)(hS + j1 * BT + 64 + 4 * bg);
            const float bhr = auxS[j1], bhz = auxS[100 + j1], bhn = auxS[200 + j1];
            #pragma unroll
            for (int i = 0; i < 8; ++i)
                hn1[i] = gru_cell(gr[i], gz[i], gn[i],
                                  R[i] + bhr, Z[i] + bhz, N[i] + bhn, ho[i]);
        }

        __syncthreads();
        *(float4*)(hS + j0 * BT + 4 * bg)      = *(float4*)(hn0);
        *(float4*)(hS + j0 * BT + 64 + 4 * bg) = *(float4*)(hn0 + 4);
        *(float4*)(hS + j1 * BT + 4 * bg)      = *(float4*)(hn1);
        *(float4*)(hS + j1 * BT + 64 + 4 * bg) = *(float4*)(hn1 + 4);
        __syncthreads();
    }

    // ret = h2 @ W_lin^T + b_lin : one thread per batch element
    if (tid < BT) {
        float acc = blin[0];
        #pragma unroll 10
        for (int k = 0; k < HID; ++k) acc += hS[k * BT + tid] * auxS[304 + k];
        g_VBUF[(size_t)(T + iter) * B + bg0 + tid] = acc;
        out[(bg0 + tid) * NB + iter] = acc;
    }
}

extern "C" void kernel_launch(void* const* d_in, const int* in_sizes, int n_in,
                              void* d_out, int out_size)
{
    const float* x    = (const float*)d_in[0];
    const float* Wih0 = (const float*)d_in[1];
    const float* Whh0 = (const float*)d_in[2];
    const float* bih0 = (const float*)d_in[3];
    const float* bhh0 = (const float*)d_in[4];
    const float* Wih1 = (const float*)d_in[5];
    const float* Whh1 = (const float*)d_in[6];
    const float* bih1 = (const float*)d_in[7];
    const float* bhh1 = (const float*)d_in[8];
    const float* Wlin = (const float*)d_in[9];
    const float* blin = (const float*)d_in[10];
    float* out = (float*)d_out;

    const int B = in_sizes[0] / T;              // 65536
    const int smem = SMEM_FLOATS * (int)sizeof(float);

    cudaFuncSetAttribute(k_layer0, cudaFuncAttributeMaxDynamicSharedMemorySize, smem);
    cudaFuncSetAttribute(k_gi1,    cudaFuncAttributeMaxDynamicSharedMemorySize, smem);
    cudaFuncSetAttribute(k_layer1, cudaFuncAttributeMaxDynamicSharedMemorySize, smem);

    k_init<<<(B * T + 511) / 512, 512>>>(x, B);

    const int nblk = B / BT;                    // 512 CTAs
    for (int i = 0; i < NB; ++i) {
        k_layer0<<<nblk, NTH, smem>>>(Whh0, Wih0, bih0, bhh0, i, B);
        k_gi1  <<<nblk, NTH, smem>>>(Wih1, bih1, B);
        k_layer1<<<nblk, NTH, smem>>>(Whh1, bhh1, Wlin, blin, out, i, B);
    }
}

// round 9
// speedup vs baseline: 1.0465x; 1.0465x over previous
#include <cuda_runtime.h>

#define HID 100
#define T   10
#define NB  5
#define G3  300
#define BT  64            // batch tile per CTA
#define NTH 400           // 50 jp-lanes * 8 batch-groups
#define B_MAX 65536

// SMEM float offsets
#define OFF_W 0           // 30000 floats : W6 [k=100][jp=50][6] = r0,z0,n0,r1,z1,n1
#define OFF_H 30000       // 6400 floats  : h [k=100][64]
#define OFF_A 36400       // 1024 floats  : aux
#define SMEM_FLOATS 37424 // 149696 bytes

// Scratch (static device memory; kernel_launch stays allocation-free)
__device__ float g_VBUF[(T + NB) * B_MAX];   // sliding input window [slot][b]
__device__ float g_H1[T * HID * B_MAX];      // layer0 outputs [t][j][b]
__device__ float g_GI1[T * G3 * B_MAX];      // layer1 input gates [t][g][b]

__device__ __forceinline__ float sigf(float x)   { return 1.f / (1.f + __expf(-x)); }
__device__ __forceinline__ float tanhf_(float x) { return 1.f - 2.f / (__expf(2.f * x) + 1.f); }

// ---- packed fp32x2 helpers ----
#define PACK2(d, s) asm("mov.b64 %0, {%1, %1};" : "=l"(d) : "f"(s))
#define FMA2(acc, a, b) asm("fma.rn.f32x2 %0, %1, %2, %0;" : "+l"(acc) : "l"(a), "l"(b))
#define UNPACK2(lo, hi, v) asm("mov.b64 {%0, %1}, %2;" : "=f"(lo), "=f"(hi) : "l"(v))

// Accumulator index: [j(2)][gate(3)][q(4)]
#define AIX(j, g, q) ((j) * 12 + (g) * 4 + (q))

// Software-pipelined matvec: per k, 24 FFMA2 (k) overlap the 5 LDS (k+1).
__device__ __forceinline__ void matvec_jp(const float* __restrict__ WtS,
                                          const float* __restrict__ hS,
                                          int jp, int bg,
                                          unsigned long long acc[24])
{
    #pragma unroll
    for (int i = 0; i < 24; ++i) acc[i] = 0ull;
    const float2* __restrict__ wb = (const float2*)(WtS + jp * 6);
    const float*  __restrict__ hb = hS + 4 * bg;

    // prologue: k = 0 operands
    float2 w01 = wb[0], w23 = wb[1], w45 = wb[2];
    ulonglong2 hl = *(const ulonglong2*)(hb);
    ulonglong2 hh = *(const ulonglong2*)(hb + 32);

    #pragma unroll 4
    for (int k = 0; k < HID; ++k) {
        // prefetch k+1 while k's FMAs run
        float2 nw01, nw23, nw45;
        ulonglong2 nhl, nhh;
        if (k + 1 < HID) {
            const float2* wn = wb + (size_t)(k + 1) * 150;
            nw01 = wn[0]; nw23 = wn[1]; nw45 = wn[2];
            const float* hn = hb + (size_t)(k + 1) * 64;
            nhl = *(const ulonglong2*)(hn);
            nhh = *(const ulonglong2*)(hn + 32);
        }

        unsigned long long wr0, wz0, wn0, wr1, wz1, wn1;
        PACK2(wr0, w01.x); PACK2(wz0, w01.y); PACK2(wn0, w23.x);
        PACK2(wr1, w23.y); PACK2(wz1, w45.x); PACK2(wn1, w45.y);

        FMA2(acc[AIX(0,0,0)], hl.x, wr0); FMA2(acc[AIX(0,0,1)], hl.y, wr0);
        FMA2(acc[AIX(0,0,2)], hh.x, wr0); FMA2(acc[AIX(0,0,3)], hh.y, wr0);
        FMA2(acc[AIX(0,1,0)], hl.x, wz0); FMA2(acc[AIX(0,1,1)], hl.y, wz0);
        FMA2(acc[AIX(0,1,2)], hh.x, wz0); FMA2(acc[AIX(0,1,3)], hh.y, wz0);
        FMA2(acc[AIX(0,2,0)], hl.x, wn0); FMA2(acc[AIX(0,2,1)], hl.y, wn0);
        FMA2(acc[AIX(0,2,2)], hh.x, wn0); FMA2(acc[AIX(0,2,3)], hh.y, wn0);
        FMA2(acc[AIX(1,0,0)], hl.x, wr1); FMA2(acc[AIX(1,0,1)], hl.y, wr1);
        FMA2(acc[AIX(1,0,2)], hh.x, wr1); FMA2(acc[AIX(1,0,3)], hh.y, wr1);
        FMA2(acc[AIX(1,1,0)], hl.x, wz1); FMA2(acc[AIX(1,1,1)], hl.y, wz1);
        FMA2(acc[AIX(1,1,2)], hh.x, wz1); FMA2(acc[AIX(1,1,3)], hh.y, wz1);
        FMA2(acc[AIX(1,2,0)], hl.x, wn1); FMA2(acc[AIX(1,2,1)], hl.y, wn1);
        FMA2(acc[AIX(1,2,2)], hh.x, wn1); FMA2(acc[AIX(1,2,3)], hh.y, wn1);

        w01 = nw01; w23 = nw23; w45 = nw45;
        hl = nhl; hh = nhh;
    }
}

// Global W [g=300][k=100] -> smem W6 [k][jp][6], slot = (j&1)*3 + gate
__device__ __forceinline__ void load_weight6(const float* __restrict__ W,
                                             float* __restrict__ WtS, int tid)
{
    for (int idx = tid; idx < G3 * HID; idx += NTH) {
        int g = idx / HID;
        int k = idx - g * HID;
        int gate = g / HID;
        int j    = g - gate * HID;
        WtS[k * G3 + (j >> 1) * 6 + (j & 1) * 3 + gate] = W[idx];
    }
}

__device__ __forceinline__ float gru_cell(float gi_r, float gi_z, float gi_n,
                                          float gr, float gz, float gn, float hold)
{
    float r = sigf(gi_r + gr);
    float z = sigf(gi_z + gz);
    float n = tanhf_(gi_n + r * gn);
    return (1.f - z) * n + z * hold;
}

// unpack one j's 12 accumulators into 8 floats per gate
#define UNPACK_J(jj, R, Z, N, acc) \
    UNPACK2(R[0], R[1], acc[AIX(jj,0,0)]); UNPACK2(R[2], R[3], acc[AIX(jj,0,1)]); \
    UNPACK2(R[4], R[5], acc[AIX(jj,0,2)]); UNPACK2(R[6], R[7], acc[AIX(jj,0,3)]); \
    UNPACK2(Z[0], Z[1], acc[AIX(jj,1,0)]); UNPACK2(Z[2], Z[3], acc[AIX(jj,1,1)]); \
    UNPACK2(Z[4], Z[5], acc[AIX(jj,1,2)]); UNPACK2(Z[6], Z[7], acc[AIX(jj,1,3)]); \
    UNPACK2(N[0], N[1], acc[AIX(jj,2,0)]); UNPACK2(N[2], N[3], acc[AIX(jj,2,1)]); \
    UNPACK2(N[4], N[5], acc[AIX(jj,2,2)]); UNPACK2(N[6], N[7], acc[AIX(jj,2,3)])

// ---------------- init: VBUF[s][b] = x[b][s] ----------------
__global__ void k_init(const float* __restrict__ x, int B)
{
    int idx = blockIdx.x * blockDim.x + threadIdx.x;
    if (idx < B * T) {
        int b = idx / T, s = idx - b * T;
        g_VBUF[s * B + b] = x[idx];
    }
}

// ---------------- K1: layer-0 recurrence ----------------
__global__ void __launch_bounds__(NTH, 1)
k_layer0(const float* __restrict__ Whh0, const float* __restrict__ Wih0,
         const float* __restrict__ bih0, const float* __restrict__ bhh0,
         int iter, int B)
{
    extern __shared__ float sm[];
    float* WtS = sm + OFF_W;
    float* hS  = sm + OFF_H;
    float* auxS = sm + OFF_A;   // [0:300) wih, [304:604) bih, [608:908) bhh

    const int tid = threadIdx.x;
    const int jp  = tid >> 3;
    const int bg  = tid & 7;
    const int bg0 = blockIdx.x * BT;
    const int j0  = 2 * jp, j1 = 2 * jp + 1;

    load_weight6(Whh0, WtS, tid);
    for (int idx = tid; idx < G3; idx += NTH) {
        auxS[idx]       = Wih0[idx];
        auxS[304 + idx] = bih0[idx];
        auxS[608 + idx] = bhh0[idx];
    }
    for (int idx = tid; idx < HID * BT; idx += NTH) hS[idx] = 0.f;
    __syncthreads();

    const float wir0 = auxS[j0],       wiz0 = auxS[100 + j0], win0 = auxS[200 + j0];
    const float wir1 = auxS[j1],       wiz1 = auxS[100 + j1], win1 = auxS[200 + j1];
    const float bir0 = auxS[304 + j0], biz0 = auxS[404 + j0], bin0 = auxS[504 + j0];
    const float bir1 = auxS[304 + j1], biz1 = auxS[404 + j1], bin1 = auxS[504 + j1];
    const float bhr0 = auxS[608 + j0], bhz0 = auxS[708 + j0], bhn0 = auxS[808 + j0];
    const float bhr1 = auxS[608 + j1], bhz1 = auxS[708 + j1], bhn1 = auxS[808 + j1];

    for (int t = 0; t < T; ++t) {
        unsigned long long acc[24];
        matvec_jp(WtS, hS, jp, bg, acc);

        const float* xb = g_VBUF + (size_t)(iter + t) * B + bg0 + 4 * bg;
        float4 xlo = *(const float4*)xb;
        float4 xhi = *(const float4*)(xb + 32);
        float xv[8] = {xlo.x, xlo.y, xlo.z, xlo.w, xhi.x, xhi.y, xhi.z, xhi.w};

        float h0o[8], h1o[8];
        *(float4*)(h0o)     = *(const float4*)(hS + j0 * 64 + 4 * bg);
        *(float4*)(h0o + 4) = *(const float4*)(hS + j0 * 64 + 32 + 4 * bg);
        *(float4*)(h1o)     = *(const float4*)(hS + j1 * 64 + 4 * bg);
        *(float4*)(h1o + 4) = *(const float4*)(hS + j1 * 64 + 32 + 4 * bg);

        float R[8], Z[8], N[8], hn0[8], hn1[8];
        UNPACK_J(0, R, Z, N, acc);
        #pragma unroll
        for (int i = 0; i < 8; ++i)
            hn0[i] = gru_cell(xv[i]*wir0 + bir0, xv[i]*wiz0 + biz0, xv[i]*win0 + bin0,
                              R[i] + bhr0, Z[i] + bhz0, N[i] + bhn0, h0o[i]);
        UNPACK_J(1, R, Z, N, acc);
        #pragma unroll
        for (int i = 0; i < 8; ++i)
            hn1[i] = gru_cell(xv[i]*wir1 + bir1, xv[i]*wiz1 + biz1, xv[i]*win1 + bin1,
                              R[i] + bhr1, Z[i] + bhz1, N[i] + bhn1, h1o[i]);

        __syncthreads();   // all matvec/h_old reads of hS complete
        *(float4*)(hS + j0 * 64 + 4 * bg)      = *(float4*)(hn0);
        *(float4*)(hS + j0 * 64 + 32 + 4 * bg) = *(float4*)(hn0 + 4);
        *(float4*)(hS + j1 * 64 + 4 * bg)      = *(float4*)(hn1);
        *(float4*)(hS + j1 * 64 + 32 + 4 * bg) = *(float4*)(hn1 + 4);
        float* gw0 = g_H1 + (size_t)(t * HID + j0) * B + bg0 + 4 * bg;
        float* gw1 = g_H1 + (size_t)(t * HID + j1) * B + bg0 + 4 * bg;
        *(float4*)(gw0)      = *(float4*)(hn0);
        *(float4*)(gw0 + 32) = *(float4*)(hn0 + 4);
        *(float4*)(gw1)      = *(float4*)(hn1);
        *(float4*)(gw1 + 32) = *(float4*)(hn1 + 4);
        __syncthreads();
    }
}

// ---------------- K2: GI1[t] = Wih1 * H1[t] + b_ih1 (loops all t) ----------------
__global__ void __launch_bounds__(NTH, 1)
k_gi1(const float* __restrict__ Wih1, const float* __restrict__ bih1, int B)
{
    extern __shared__ float sm[];
    float* WtS  = sm + OFF_W;
    float* hS   = sm + OFF_H;
    float* auxS = sm + OFF_A;

    const int tid = threadIdx.x;
    const int jp  = tid >> 3;
    const int bg  = tid & 7;
    const int bg0 = blockIdx.x * BT;
    const int j0  = 2 * jp, j1 = 2 * jp + 1;

    load_weight6(Wih1, WtS, tid);
    for (int idx = tid; idx < G3; idx += NTH) auxS[idx] = bih1[idx];
    __syncthreads();

    const float br0 = auxS[j0], bz0 = auxS[100 + j0], bn0 = auxS[200 + j0];
    const float br1 = auxS[j1], bz1 = auxS[100 + j1], bn1 = auxS[200 + j1];

    for (int t = 0; t < T; ++t) {
        // stage H1[t]
        for (int idx = tid * 4; idx < HID * BT; idx += NTH * 4)
            *(float4*)(hS + idx) = *(const float4*)(g_H1 + (size_t)t * HID * B
                                      + (size_t)(idx >> 6) * B + bg0 + (idx & 63));
        __syncthreads();

        unsigned long long acc[24];
        matvec_jp(WtS, hS, jp, bg, acc);

        float R[8], Z[8], N[8];
        float* gbase = g_GI1 + (size_t)t * G3 * B + bg0 + 4 * bg;
        UNPACK_J(0, R, Z, N, acc);
        { float* p = gbase + (size_t)j0 * B;
          *(float4*)(p)      = make_float4(R[0]+br0, R[1]+br0, R[2]+br0, R[3]+br0);
          *(float4*)(p + 32) = make_float4(R[4]+br0, R[5]+br0, R[6]+br0, R[7]+br0);
          p = gbase + (size_t)(100 + j0) * B;
          *(float4*)(p)      = make_float4(Z[0]+bz0, Z[1]+bz0, Z[2]+bz0, Z[3]+bz0);
          *(float4*)(p + 32) = make_float4(Z[4]+bz0, Z[5]+bz0, Z[6]+bz0, Z[7]+bz0);
          p = gbase + (size_t)(200 + j0) * B;
          *(float4*)(p)      = make_float4(N[0]+bn0, N[1]+bn0, N[2]+bn0, N[3]+bn0);
          *(float4*)(p + 32) = make_float4(N[4]+bn0, N[5]+bn0, N[6]+bn0, N[7]+bn0); }
        UNPACK_J(1, R, Z, N, acc);
        { float* p = gbase + (size_t)j1 * B;
          *(float4*)(p)      = make_float4(R[0]+br1, R[1]+br1, R[2]+br1, R[3]+br1);
          *(float4*)(p + 32) = make_float4(R[4]+br1, R[5]+br1, R[6]+br1, R[7]+br1);
          p = gbase + (size_t)(100 + j1) * B;
          *(float4*)(p)      = make_float4(Z[0]+bz1, Z[1]+bz1, Z[2]+bz1, Z[3]+bz1);
          *(float4*)(p + 32) = make_float4(Z[4]+bz1, Z[5]+bz1, Z[6]+bz1, Z[7]+bz1);
          p = gbase + (size_t)(200 + j1) * B;
          *(float4*)(p)      = make_float4(N[0]+bn1, N[1]+bn1, N[2]+bn1, N[3]+bn1);
          *(float4*)(p + 32) = make_float4(N[4]+bn1, N[5]+bn1, N[6]+bn1, N[7]+bn1); }
        __syncthreads();
    }
}

// ---------------- K3: layer-1 recurrence + final linear ----------------
__global__ void __launch_bounds__(NTH, 1)
k_layer1(const float* __restrict__ Whh1, const float* __restrict__ bhh1,
         const float* __restrict__ Wlin, const float* __restrict__ blin,
         float* __restrict__ out, int iter, int B)
{
    extern __shared__ float sm[];
    float* WtS  = sm + OFF_W;
    float* hS   = sm + OFF_H;
    float* auxS = sm + OFF_A;   // [0:300) bhh, [304:404) wlin

    const int tid = threadIdx.x;
    const int jp  = tid >> 3;
    const int bg  = tid & 7;
    const int bg0 = blockIdx.x * BT;
    const int j0  = 2 * jp, j1 = 2 * jp + 1;

    load_weight6(Whh1, WtS, tid);
    for (int idx = tid; idx < G3; idx += NTH) auxS[idx] = bhh1[idx];
    for (int idx = tid; idx < HID; idx += NTH) auxS[304 + idx] = Wlin[idx];
    for (int idx = tid; idx < HID * BT; idx += NTH) hS[idx] = 0.f;
    __syncthreads();

    const float bhr0 = auxS[j0], bhz0 = auxS[100 + j0], bhn0 = auxS[200 + j0];
    const float bhr1 = auxS[j1], bhz1 = auxS[100 + j1], bhn1 = auxS[200 + j1];

    for (int t = 0; t < T; ++t) {
        unsigned long long acc[24];
        matvec_jp(WtS, hS, jp, bg, acc);

        const float* gbase = g_GI1 + (size_t)t * G3 * B + bg0 + 4 * bg;
        float hn0[8], hn1[8];
        {   float R[8], Z[8], N[8], ho[8], gr[8], gz[8], gn[8];
            UNPACK_J(0, R, Z, N, acc);
            *(float4*)(gr)     = *(const float4*)(gbase + (size_t)j0 * B);
            *(float4*)(gr + 4) = *(const float4*)(gbase + (size_t)j0 * B + 32);
            *(float4*)(gz)     = *(const float4*)(gbase + (size_t)(100 + j0) * B);
            *(float4*)(gz + 4) = *(const float4*)(gbase + (size_t)(100 + j0) * B + 32);
            *(float4*)(gn)     = *(const float4*)(gbase + (size_t)(200 + j0) * B);
            *(float4*)(gn + 4) = *(const float4*)(gbase + (size_t)(200 + j0) * B + 32);
            *(float4*)(ho)     = *(const float4*)(hS + j0 * 64 + 4 * bg);
            *(float4*)(ho + 4) = *(const float4*)(hS + j0 * 64 + 32 + 4 * bg);
            #pragma unroll
            for (int i = 0; i < 8; ++i)
                hn0[i] = gru_cell(gr[i], gz[i], gn[i],
                                  R[i] + bhr0, Z[i] + bhz0, N[i] + bhn0, ho[i]);
        }
        {   float R[8], Z[8], N[8], ho[8], gr[8], gz[8], gn[8];
            UNPACK_J(1, R, Z, N, acc);
            *(float4*)(gr)     = *(const float4*)(gbase + (size_t)j1 * B);
            *(float4*)(gr + 4) = *(const float4*)(gbase + (size_t)j1 * B + 32);
            *(float4*)(gz)     = *(const float4*)(gbase + (size_t)(100 + j1) * B);
            *(float4*)(gz + 4) = *(const float4*)(gbase + (size_t)(100 + j1) * B + 32);
            *(float4*)(gn)     = *(const float4*)(gbase + (size_t)(200 + j1) * B);
            *(float4*)(gn + 4) = *(const float4*)(gbase + (size_t)(200 + j1) * B + 32);
            *(float4*)(ho)     = *(const float4*)(hS + j1 * 64 + 4 * bg);
            *(float4*)(ho + 4) = *(const float4*)(hS + j1 * 64 + 32 + 4 * bg);
            #pragma unroll
            for (int i = 0; i < 8; ++i)
                hn1[i] = gru_cell(gr[i], gz[i], gn[i],
                                  R[i] + bhr1, Z[i] + bhz1, N[i] + bhn1, ho[i]);
        }

        __syncthreads();
        *(float4*)(hS + j0 * 64 + 4 * bg)      = *(float4*)(hn0);
        *(float4*)(hS + j0 * 64 + 32 + 4 * bg) = *(float4*)(hn0 + 4);
        *(float4*)(hS + j1 * 64 + 4 * bg)      = *(float4*)(hn1);
        *(float4*)(hS + j1 * 64 + 32 + 4 * bg) = *(float4*)(hn1 + 4);
        __syncthreads();
    }

    // ret = h2 @ W_lin^T + b_lin : one thread per batch element
    if (tid < BT) {
        float acc = blin[0];
        #pragma unroll 10
        for (int k = 0; k < HID; ++k) acc += hS[k * 64 + tid] * auxS[304 + k];
        g_VBUF[(size_t)(T + iter) * B + bg0 + tid] = acc;
        out[(bg0 + tid) * NB + iter] = acc;
    }
}

extern "C" void kernel_launch(void* const* d_in, const int* in_sizes, int n_in,
                              void* d_out, int out_size)
{
    const float* x    = (const float*)d_in[0];
    const float* Wih0 = (const float*)d_in[1];
    const float* Whh0 = (const float*)d_in[2];
    const float* bih0 = (const float*)d_in[3];
    const float* bhh0 = (const float*)d_in[4];
    const float* Wih1 = (const float*)d_in[5];
    const float* Whh1 = (const float*)d_in[6];
    const float* bih1 = (const float*)d_in[7];
    const float* bhh1 = (const float*)d_in[8];
    const float* Wlin = (const float*)d_in[9];
    const float* blin = (const float*)d_in[10];
    float* out = (float*)d_out;

    const int B = in_sizes[0] / T;              // 65536
    const int smem = SMEM_FLOATS * (int)sizeof(float);

    cudaFuncSetAttribute(k_layer0, cudaFuncAttributeMaxDynamicSharedMemorySize, smem);
    cudaFuncSetAttribute(k_gi1,    cudaFuncAttributeMaxDynamicSharedMemorySize, smem);
    cudaFuncSetAttribute(k_layer1, cudaFuncAttributeMaxDynamicSharedMemorySize, smem);

    k_init<<<(B * T + 511) / 512, 512>>>(x, B);

    const int nblk = B / BT;                    // 1024 CTAs, ~6.92 waves
    for (int i = 0; i < NB; ++i) {
        k_layer0<<<nblk, NTH, smem>>>(Whh0, Wih0, bih0, bhh0, i, B);
        k_gi1  <<<nblk, NTH, smem>>>(Wih1, bih1, B);
        k_layer1<<<nblk, NTH, smem>>>(Whh1, bhh1, Wlin, blin, out, i, B);
    }
}

// round 10
// speedup vs baseline: 1.0469x; 1.0004x over previous
#include <cuda_runtime.h>

#define HID 100
#define T   10
#define NB  5
#define G3  300
#define BT  64            // batch tile per CTA
#define NTH 400           // 50 jp-lanes * 8 batch-groups
#define B_MAX 65536

// SMEM float offsets
#define OFF_W 0           // 30000 floats : W6 [k=100][jp=50][6] = r0,z0,n0,r1,z1,n1
#define OFF_H 30000       // 6400 floats  : h [k=100][64]
#define OFF_A 36400       // 1024 floats  : aux
#define SMEM_FLOATS 37424 // 149696 bytes

// Scratch (static device memory; kernel_launch stays allocation-free)
__device__ float g_VBUF[(T + NB) * B_MAX];   // sliding input window [slot][b]
__device__ float g_H1[T * HID * B_MAX];      // layer0 outputs [t][j][b]
__device__ float g_GI1[T * G3 * B_MAX];      // layer1 input gates [t][g][b]

__device__ __forceinline__ float sigf(float x)   { return 1.f / (1.f + __expf(-x)); }
__device__ __forceinline__ float tanhf_(float x) { return 1.f - 2.f / (__expf(2.f * x) + 1.f); }

// ---- packed fp32x2 helpers ----
#define PACK2(d, s) asm("mov.b64 %0, {%1, %1};" : "=l"(d) : "f"(s))
#define FMA2(acc, a, b) asm("fma.rn.f32x2 %0, %1, %2, %0;" : "+l"(acc) : "l"(a), "l"(b))
#define UNPACK2(lo, hi, v) asm("mov.b64 {%0, %1}, %2;" : "=f"(lo), "=f"(hi) : "l"(v))

// Accumulator index: [j(2)][gate(3)][q(4)]
#define AIX(j, g, q) ((j) * 12 + (g) * 4 + (q))

// Software-pipelined matvec: per k, 24 FFMA2 (k) overlap the 5 LDS (k+1).
__device__ __forceinline__ void matvec_jp(const float* __restrict__ WtS,
                                          const float* __restrict__ hS,
                                          int jp, int bg,
                                          unsigned long long acc[24])
{
    #pragma unroll
    for (int i = 0; i < 24; ++i) acc[i] = 0ull;
    const float2* __restrict__ wb = (const float2*)(WtS + jp * 6);
    const float*  __restrict__ hb = hS + 4 * bg;

    // prologue: k = 0 operands
    float2 w01 = wb[0], w23 = wb[1], w45 = wb[2];
    ulonglong2 hl = *(const ulonglong2*)(hb);
    ulonglong2 hh = *(const ulonglong2*)(hb + 32);

    #pragma unroll 4
    for (int k = 0; k < HID; ++k) {
        // prefetch k+1 while k's FMAs run
        float2 nw01, nw23, nw45;
        ulonglong2 nhl, nhh;
        if (k + 1 < HID) {
            const float2* wn = wb + (size_t)(k + 1) * 150;
            nw01 = wn[0]; nw23 = wn[1]; nw45 = wn[2];
            const float* hn = hb + (size_t)(k + 1) * 64;
            nhl = *(const ulonglong2*)(hn);
            nhh = *(const ulonglong2*)(hn + 32);
        }

        unsigned long long wr0, wz0, wn0, wr1, wz1, wn1;
        PACK2(wr0, w01.x); PACK2(wz0, w01.y); PACK2(wn0, w23.x);
        PACK2(wr1, w23.y); PACK2(wz1, w45.x); PACK2(wn1, w45.y);

        FMA2(acc[AIX(0,0,0)], hl.x, wr0); FMA2(acc[AIX(0,0,1)], hl.y, wr0);
        FMA2(acc[AIX(0,0,2)], hh.x, wr0); FMA2(acc[AIX(0,0,3)], hh.y, wr0);
        FMA2(acc[AIX(0,1,0)], hl.x, wz0); FMA2(acc[AIX(0,1,1)], hl.y, wz0);
        FMA2(acc[AIX(0,1,2)], hh.x, wz0); FMA2(acc[AIX(0,1,3)], hh.y, wz0);
        FMA2(acc[AIX(0,2,0)], hl.x, wn0); FMA2(acc[AIX(0,2,1)], hl.y, wn0);
        FMA2(acc[AIX(0,2,2)], hh.x, wn0); FMA2(acc[AIX(0,2,3)], hh.y, wn0);
        FMA2(acc[AIX(1,0,0)], hl.x, wr1); FMA2(acc[AIX(1,0,1)], hl.y, wr1);
        FMA2(acc[AIX(1,0,2)], hh.x, wr1); FMA2(acc[AIX(1,0,3)], hh.y, wr1);
        FMA2(acc[AIX(1,1,0)], hl.x, wz1); FMA2(acc[AIX(1,1,1)], hl.y, wz1);
        FMA2(acc[AIX(1,1,2)], hh.x, wz1); FMA2(acc[AIX(1,1,3)], hh.y, wz1);
        FMA2(acc[AIX(1,2,0)], hl.x, wn1); FMA2(acc[AIX(1,2,1)], hl.y, wn1);
        FMA2(acc[AIX(1,2,2)], hh.x, wn1); FMA2(acc[AIX(1,2,3)], hh.y, wn1);

        w01 = nw01; w23 = nw23; w45 = nw45;
        hl = nhl; hh = nhh;
    }
}

// Global W [g=300][k=100] -> smem W6 [k][jp][6], slot = (j&1)*3 + gate
__device__ __forceinline__ void load_weight6(const float* __restrict__ W,
                                             float* __restrict__ WtS, int tid)
{
    for (int idx = tid; idx < G3 * HID; idx += NTH) {
        int g = idx / HID;
        int k = idx - g * HID;
        int gate = g / HID;
        int j    = g - gate * HID;
        WtS[k * G3 + (j >> 1) * 6 + (j & 1) * 3 + gate] = W[idx];
    }
}

__device__ __forceinline__ float gru_cell(float gi_r, float gi_z, float gi_n,
                                          float gr, float gz, float gn, float hold)
{
    float r = sigf(gi_r + gr);
    float z = sigf(gi_z + gz);
    float n = tanhf_(gi_n + r * gn);
    return (1.f - z) * n + z * hold;
}

// unpack one j's 12 accumulators into 8 floats per gate
#define UNPACK_J(jj, R, Z, N, acc) \
    UNPACK2(R[0], R[1], acc[AIX(jj,0,0)]); UNPACK2(R[2], R[3], acc[AIX(jj,0,1)]); \
    UNPACK2(R[4], R[5], acc[AIX(jj,0,2)]); UNPACK2(R[6], R[7], acc[AIX(jj,0,3)]); \
    UNPACK2(Z[0], Z[1], acc[AIX(jj,1,0)]); UNPACK2(Z[2], Z[3], acc[AIX(jj,1,1)]); \
    UNPACK2(Z[4], Z[5], acc[AIX(jj,1,2)]); UNPACK2(Z[6], Z[7], acc[AIX(jj,1,3)]); \
    UNPACK2(N[0], N[1], acc[AIX(jj,2,0)]); UNPACK2(N[2], N[3], acc[AIX(jj,2,1)]); \
    UNPACK2(N[4], N[5], acc[AIX(jj,2,2)]); UNPACK2(N[6], N[7], acc[AIX(jj,2,3)])

// ---------------- init: VBUF[s][b] = x[b][s] ----------------
__global__ void k_init(const float* __restrict__ x, int B)
{
    int idx = blockIdx.x * blockDim.x + threadIdx.x;
    if (idx < B * T) {
        int b = idx / T, s = idx - b * T;
        g_VBUF[s * B + b] = x[idx];
    }
}

// ---------------- K1: layer-0 recurrence ----------------
__global__ void __launch_bounds__(NTH, 1)
k_layer0(const float* __restrict__ Whh0, const float* __restrict__ Wih0,
         const float* __restrict__ bih0, const float* __restrict__ bhh0,
         int iter, int B)
{
    extern __shared__ float sm[];
    float* WtS = sm + OFF_W;
    float* hS  = sm + OFF_H;
    float* auxS = sm + OFF_A;   // [0:300) wih, [304:604) bih, [608:908) bhh

    const int tid = threadIdx.x;
    const int jp  = tid >> 3;
    const int bg  = tid & 7;
    const int bg0 = blockIdx.x * BT;
    const int j0  = 2 * jp, j1 = 2 * jp + 1;

    load_weight6(Whh0, WtS, tid);
    for (int idx = tid; idx < G3; idx += NTH) {
        auxS[idx]       = Wih0[idx];
        auxS[304 + idx] = bih0[idx];
        auxS[608 + idx] = bhh0[idx];
    }
    for (int idx = tid; idx < HID * BT; idx += NTH) hS[idx] = 0.f;
    __syncthreads();

    const float wir0 = auxS[j0],       wiz0 = auxS[100 + j0], win0 = auxS[200 + j0];
    const float wir1 = auxS[j1],       wiz1 = auxS[100 + j1], win1 = auxS[200 + j1];
    const float bir0 = auxS[304 + j0], biz0 = auxS[404 + j0], bin0 = auxS[504 + j0];
    const float bir1 = auxS[304 + j1], biz1 = auxS[404 + j1], bin1 = auxS[504 + j1];
    const float bhr0 = auxS[608 + j0], bhz0 = auxS[708 + j0], bhn0 = auxS[808 + j0];
    const float bhr1 = auxS[608 + j1], bhz1 = auxS[708 + j1], bhn1 = auxS[808 + j1];

    for (int t = 0; t < T; ++t) {
        unsigned long long acc[24];
        matvec_jp(WtS, hS, jp, bg, acc);

        const float* xb = g_VBUF + (size_t)(iter + t) * B + bg0 + 4 * bg;
        float4 xlo = *(const float4*)xb;
        float4 xhi = *(const float4*)(xb + 32);
        float xv[8] = {xlo.x, xlo.y, xlo.z, xlo.w, xhi.x, xhi.y, xhi.z, xhi.w};

        float h0o[8], h1o[8];
        *(float4*)(h0o)     = *(const float4*)(hS + j0 * 64 + 4 * bg);
        *(float4*)(h0o + 4) = *(const float4*)(hS + j0 * 64 + 32 + 4 * bg);
        *(float4*)(h1o)     = *(const float4*)(hS + j1 * 64 + 4 * bg);
        *(float4*)(h1o + 4) = *(const float4*)(hS + j1 * 64 + 32 + 4 * bg);

        float R[8], Z[8], N[8], hn0[8], hn1[8];
        UNPACK_J(0, R, Z, N, acc);
        #pragma unroll
        for (int i = 0; i < 8; ++i)
            hn0[i] = gru_cell(xv[i]*wir0 + bir0, xv[i]*wiz0 + biz0, xv[i]*win0 + bin0,
                              R[i] + bhr0, Z[i] + bhz0, N[i] + bhn0, h0o[i]);
        UNPACK_J(1, R, Z, N, acc);
        #pragma unroll
        for (int i = 0; i < 8; ++i)
            hn1[i] = gru_cell(xv[i]*wir1 + bir1, xv[i]*wiz1 + biz1, xv[i]*win1 + bin1,
                              R[i] + bhr1, Z[i] + bhz1, N[i] + bhn1, h1o[i]);

        __syncthreads();   // all matvec/h_old reads of hS complete
        *(float4*)(hS + j0 * 64 + 4 * bg)      = *(float4*)(hn0);
        *(float4*)(hS + j0 * 64 + 32 + 4 * bg) = *(float4*)(hn0 + 4);
        *(float4*)(hS + j1 * 64 + 4 * bg)      = *(float4*)(hn1);
        *(float4*)(hS + j1 * 64 + 32 + 4 * bg) = *(float4*)(hn1 + 4);
        float* gw0 = g_H1 + (size_t)(t * HID + j0) * B + bg0 + 4 * bg;
        float* gw1 = g_H1 + (size_t)(t * HID + j1) * B + bg0 + 4 * bg;
        *(float4*)(gw0)      = *(float4*)(hn0);
        *(float4*)(gw0 + 32) = *(float4*)(hn0 + 4);
        *(float4*)(gw1)      = *(float4*)(hn1);
        *(float4*)(gw1 + 32) = *(float4*)(hn1 + 4);
        __syncthreads();
    }
}

// ---------------- K2: GI1[t] = Wih1 * H1[t] + b_ih1 (loops all t) ----------------
__global__ void __launch_bounds__(NTH, 1)
k_gi1(const float* __restrict__ Wih1, const float* __restrict__ bih1, int B)
{
    extern __shared__ float sm[];
    float* WtS  = sm + OFF_W;
    float* hS   = sm + OFF_H;
    float* auxS = sm + OFF_A;

    const int tid = threadIdx.x;
    const int jp  = tid >> 3;
    const int bg  = tid & 7;
    const int bg0 = blockIdx.x * BT;
    const int j0  = 2 * jp, j1 = 2 * jp + 1;

    load_weight6(Wih1, WtS, tid);
    for (int idx = tid; idx < G3; idx += NTH) auxS[idx] = bih1[idx];
    __syncthreads();

    const float br0 = auxS[j0], bz0 = auxS[100 + j0], bn0 = auxS[200 + j0];
    const float br1 = auxS[j1], bz1 = auxS[100 + j1], bn1 = auxS[200 + j1];

    for (int t = 0; t < T; ++t) {
        // stage H1[t]
        for (int idx = tid * 4; idx < HID * BT; idx += NTH * 4)
            *(float4*)(hS + idx) = *(const float4*)(g_H1 + (size_t)t * HID * B
                                      + (size_t)(idx >> 6) * B + bg0 + (idx & 63));
        __syncthreads();

        unsigned long long acc[24];
        matvec_jp(WtS, hS, jp, bg, acc);

        float R[8], Z[8], N[8];
        float* gbase = g_GI1 + (size_t)t * G3 * B + bg0 + 4 * bg;
        UNPACK_J(0, R, Z, N, acc);
        { float* p = gbase + (size_t)j0 * B;
          *(float4*)(p)      = make_float4(R[0]+br0, R[1]+br0, R[2]+br0, R[3]+br0);
          *(float4*)(p + 32) = make_float4(R[4]+br0, R[5]+br0, R[6]+br0, R[7]+br0);
          p = gbase + (size_t)(100 + j0) * B;
          *(float4*)(p)      = make_float4(Z[0]+bz0, Z[1]+bz0, Z[2]+bz0, Z[3]+bz0);
          *(float4*)(p + 32) = make_float4(Z[4]+bz0, Z[5]+bz0, Z[6]+bz0, Z[7]+bz0);
          p = gbase + (size_t)(200 + j0) * B;
          *(float4*)(p)      = make_float4(N[0]+bn0, N[1]+bn0, N[2]+bn0, N[3]+bn0);
          *(float4*)(p + 32) = make_float4(N[4]+bn0, N[5]+bn0, N[6]+bn0, N[7]+bn0); }
        UNPACK_J(1, R, Z, N, acc);
        { float* p = gbase + (size_t)j1 * B;
          *(float4*)(p)      = make_float4(R[0]+br1, R[1]+br1, R[2]+br1, R[3]+br1);
          *(float4*)(p + 32) = make_float4(R[4]+br1, R[5]+br1, R[6]+br1, R[7]+br1);
          p = gbase + (size_t)(100 + j1) * B;
          *(float4*)(p)      = make_float4(Z[0]+bz1, Z[1]+bz1, Z[2]+bz1, Z[3]+bz1);
          *(float4*)(p + 32) = make_float4(Z[4]+bz1, Z[5]+bz1, Z[6]+bz1, Z[7]+bz1);
          p = gbase + (size_t)(200 + j1) * B;
          *(float4*)(p)      = make_float4(N[0]+bn1, N[1]+bn1, N[2]+bn1, N[3]+bn1);
          *(float4*)(p + 32) = make_float4(N[4]+bn1, N[5]+bn1, N[6]+bn1, N[7]+bn1); }
        __syncthreads();
    }
}

// ---------------- K3: layer-1 recurrence + final linear ----------------
__global__ void __launch_bounds__(NTH, 1)
k_layer1(const float* __restrict__ Whh1, const float* __restrict__ bhh1,
         const float* __restrict__ Wlin, const float* __restrict__ blin,
         float* __restrict__ out, int iter, int B)
{
    extern __shared__ float sm[];
    float* WtS  = sm + OFF_W;
    float* hS   = sm + OFF_H;
    float* auxS = sm + OFF_A;   // [0:300) bhh, [304:404) wlin

    const int tid = threadIdx.x;
    const int jp  = tid >> 3;
    const int bg  = tid & 7;
    const int bg0 = blockIdx.x * BT;
    const int j0  = 2 * jp, j1 = 2 * jp + 1;

    load_weight6(Whh1, WtS, tid);
    for (int idx = tid; idx < G3; idx += NTH) auxS[idx] = bhh1[idx];
    for (int idx = tid; idx < HID; idx += NTH) auxS[304 + idx] = Wlin[idx];
    for (int idx = tid; idx < HID * BT; idx += NTH) hS[idx] = 0.f;
    __syncthreads();

    const float bhr0 = auxS[j0], bhz0 = auxS[100 + j0], bhn0 = auxS[200 + j0];
    const float bhr1 = auxS[j1], bhz1 = auxS[100 + j1], bhn1 = auxS[200 + j1];

    for (int t = 0; t < T; ++t) {
        unsigned long long acc[24];
        matvec_jp(WtS, hS, jp, bg, acc);

        const float* gbase = g_GI1 + (size_t)t * G3 * B + bg0 + 4 * bg;
        float hn0[8], hn1[8];
        {   float R[8], Z[8], N[8], ho[8], gr[8], gz[8], gn[8];
            UNPACK_J(0, R, Z, N, acc);
            *(float4*)(gr)     = *(const float4*)(gbase + (size_t)j0 * B);
            *(float4*)(gr + 4) = *(const float4*)(gbase + (size_t)j0 * B + 32);
            *(float4*)(gz)     = *(const float4*)(gbase + (size_t)(100 + j0) * B);
            *(float4*)(gz + 4) = *(const float4*)(gbase + (size_t)(100 + j0) * B + 32);
            *(float4*)(gn)     = *(const float4*)(gbase + (size_t)(200 + j0) * B);
            *(float4*)(gn + 4) = *(const float4*)(gbase + (size_t)(200 + j0) * B + 32);
            *(float4*)(ho)     = *(const float4*)(hS + j0 * 64 + 4 * bg);
            *(float4*)(ho + 4) = *(const float4*)(hS + j0 * 64 + 32 + 4 * bg);
            #pragma unroll
            for (int i = 0; i < 8; ++i)
                hn0[i] = gru_cell(gr[i], gz[i], gn[i],
                                  R[i] + bhr0, Z[i] + bhz0, N[i] + bhn0, ho[i]);
        }
        {   float R[8], Z[8], N[8], ho[8], gr[8], gz[8], gn[8];
            UNPACK_J(1, R, Z, N, acc);
            *(float4*)(gr)     = *(const float4*)(gbase + (size_t)j1 * B);
            *(float4*)(gr + 4) = *(const float4*)(gbase + (size_t)j1 * B + 32);
            *(float4*)(gz)     = *(const float4*)(gbase + (size_t)(100 + j1) * B);
            *(float4*)(gz + 4) = *(const float4*)(gbase + (size_t)(100 + j1) * B + 32);
            *(float4*)(gn)     = *(const float4*)(gbase + (size_t)(200 + j1) * B);
            *(float4*)(gn + 4) = *(const float4*)(gbase + (size_t)(200 + j1) * B + 32);
            *(float4*)(ho)     = *(const float4*)(hS + j1 * 64 + 4 * bg);
            *(float4*)(ho + 4) = *(const float4*)(hS + j1 * 64 + 32 + 4 * bg);
            #pragma unroll
            for (int i = 0; i < 8; ++i)
                hn1[i] = gru_cell(gr[i], gz[i], gn[i],
                                  R[i] + bhr1, Z[i] + bhz1, N[i] + bhn1, ho[i]);
        }

        __syncthreads();
        *(float4*)(hS + j0 * 64 + 4 * bg)      = *(float4*)(hn0);
        *(float4*)(hS + j0 * 64 + 32 + 4 * bg) = *(float4*)(hn0 + 4);
        *(float4*)(hS + j1 * 64 + 4 * bg)      = *(float4*)(hn1);
        *(float4*)(hS + j1 * 64 + 32 + 4 * bg) = *(float4*)(hn1 + 4);
        __syncthreads();
    }

    // ret = h2 @ W_lin^T + b_lin : one thread per batch element
    if (tid < BT) {
        float acc = blin[0];
        #pragma unroll 10
        for (int k = 0; k < HID; ++k) acc += hS[k * 64 + tid] * auxS[304 + k];
        g_VBUF[(size_t)(T + iter) * B + bg0 + tid] = acc;
        out[(bg0 + tid) * NB + iter] = acc;
    }
}

extern "C" void kernel_launch(void* const* d_in, const int* in_sizes, int n_in,
                              void* d_out, int out_size)
{
    const float* x    = (const float*)d_in[0];
    const float* Wih0 = (const float*)d_in[1];
    const float* Whh0 = (const float*)d_in[2];
    const float* bih0 = (const float*)d_in[3];
    const float* bhh0 = (const float*)d_in[4];
    const float* Wih1 = (const float*)d_in[5];
    const float* Whh1 = (const float*)d_in[6];
    const float* bih1 = (const float*)d_in[7];
    const float* bhh1 = (const float*)d_in[8];
    const float* Wlin = (const float*)d_in[9];
    const float* blin = (const float*)d_in[10];
    float* out = (float*)d_out;

    const int B = in_sizes[0] / T;              // 65536
    const int smem = SMEM_FLOATS * (int)sizeof(float);

    cudaFuncSetAttribute(k_layer0, cudaFuncAttributeMaxDynamicSharedMemorySize, smem);
    cudaFuncSetAttribute(k_gi1,    cudaFuncAttributeMaxDynamicSharedMemorySize, smem);
    cudaFuncSetAttribute(k_layer1, cudaFuncAttributeMaxDynamicSharedMemorySize, smem);

    k_init<<<(B * T + 511) / 512, 512>>>(x, B);

    const int nblk = B / BT;                    // 1024 CTAs, ~6.92 waves
    for (int i = 0; i < NB; ++i) {
        k_layer0<<<nblk, NTH, smem>>>(Whh0, Wih0, bih0, bhh0, i, B);
        k_gi1  <<<nblk, NTH, smem>>>(Wih1, bih1, B);
        k_layer1<<<nblk, NTH, smem>>>(Whh1, bhh1, Wlin, blin, out, i, B);
    }
}

// round 11
// speedup vs baseline: 1.1748x; 1.1221x over previous
#include <cuda_runtime.h>

#define HID 100
#define T   10
#define NB  5
#define G3  300
#define BT  64            // batch tile per CTA
#define NTH 400           // 50 jp-lanes * 8 batch-groups
#define B_MAX 65536

// SMEM float offsets
#define OFF_W  0          // 30000 floats : W12 [kp=50][jp=50][12]
#define OFF_H0 30000      // 6400 floats  : h buffer 0 [k=100][64]
#define OFF_H1 36400      // 6400 floats  : h buffer 1
#define OFF_A  42800      // 1024 floats  : aux
#define SMEM_FLOATS 43824 // 175296 bytes

// Scratch (static device memory; kernel_launch stays allocation-free)
__device__ float g_VBUF[(T + NB) * B_MAX];   // sliding input window [slot][b]
__device__ float g_H1[T * HID * B_MAX];      // layer0 outputs [t][j][b]
__device__ float g_GI1[T * G3 * B_MAX];      // layer1 input gates [t][g][b]

__device__ __forceinline__ float sigf(float x)   { return 1.f / (1.f + __expf(-x)); }
__device__ __forceinline__ float tanhf_(float x) { return 1.f - 2.f / (__expf(2.f * x) + 1.f); }

// ---- packed fp32x2 helpers ----
#define PACK2(d, s) asm("mov.b64 %0, {%1, %1};" : "=l"(d) : "f"(s))
#define FMA2(acc, a, b) asm("fma.rn.f32x2 %0, %1, %2, %0;" : "+l"(acc) : "l"(a), "l"(b))
#define UNPACK2(lo, hi, v) asm("mov.b64 {%0, %1}, %2;" : "=f"(lo), "=f"(hi) : "l"(v))

// ---- cp.async helpers ----
__device__ __forceinline__ void cp16(float* smem_dst, const float* gsrc) {
    unsigned sa = (unsigned)__cvta_generic_to_shared(smem_dst);
    asm volatile("cp.async.ca.shared.global [%0], [%1], 16;" :: "r"(sa), "l"(gsrc));
}
#define CP_COMMIT() asm volatile("cp.async.commit_group;" ::: "memory")
#define CP_WAIT0()  asm volatile("cp.async.wait_group 0;" ::: "memory")

// Accumulator index: [j(2)][gate(3)][q(4)]
#define AIX(j, g, q) ((j) * 12 + (g) * 4 + (q))

#define FMA_K(jj, hl, hh, wr, wz, wn) \
    FMA2(acc[AIX(jj,0,0)], hl.x, wr); FMA2(acc[AIX(jj,0,1)], hl.y, wr); \
    FMA2(acc[AIX(jj,0,2)], hh.x, wr); FMA2(acc[AIX(jj,0,3)], hh.y, wr); \
    FMA2(acc[AIX(jj,1,0)], hl.x, wz); FMA2(acc[AIX(jj,1,1)], hl.y, wz); \
    FMA2(acc[AIX(jj,1,2)], hh.x, wz); FMA2(acc[AIX(jj,1,3)], hh.y, wz); \
    FMA2(acc[AIX(jj,2,0)], hl.x, wn); FMA2(acc[AIX(jj,2,1)], hl.y, wn); \
    FMA2(acc[AIX(jj,2,2)], hh.x, wn); FMA2(acc[AIX(jj,2,3)], hh.y, wn)

// Pair-k matvec: per kp, 3 LDS.128 (w) + 4 LDS.128 (h) + 12 PACK + 48 FFMA2 = 96 MACs
__device__ __forceinline__ void matvec2(const float* __restrict__ WtS,
                                        const float* __restrict__ hS,
                                        int jp, int bg,
                                        unsigned long long acc[24])
{
    #pragma unroll
    for (int i = 0; i < 24; ++i) acc[i] = 0ull;
    const float4* __restrict__ wb = (const float4*)(WtS + jp * 12);
    const float*  __restrict__ hb = hS + 4 * bg;
    #pragma unroll 2
    for (int kp = 0; kp < 50; ++kp) {
        float4 wa = wb[kp * 150 + 0];   // k even: r0 z0 n0 r1
        float4 wv = wb[kp * 150 + 1];   // k even: z1 n1 | k odd: r0 z0
        float4 wc = wb[kp * 150 + 2];   // k odd : n0 r1 z1 n1
        const float* h0 = hb + kp * 128;
        ulonglong2 hl0 = *(const ulonglong2*)(h0);
        ulonglong2 hh0 = *(const ulonglong2*)(h0 + 32);
        ulonglong2 hl1 = *(const ulonglong2*)(h0 + 64);
        ulonglong2 hh1 = *(const ulonglong2*)(h0 + 96);

        unsigned long long wr0, wz0, wn0, wr1, wz1, wn1;
        PACK2(wr0, wa.x); PACK2(wz0, wa.y); PACK2(wn0, wa.z);
        PACK2(wr1, wa.w); PACK2(wz1, wv.x); PACK2(wn1, wv.y);
        FMA_K(0, hl0, hh0, wr0, wz0, wn0);
        FMA_K(1, hl0, hh0, wr1, wz1, wn1);

        PACK2(wr0, wv.z); PACK2(wz0, wv.w); PACK2(wn0, wc.x);
        PACK2(wr1, wc.y); PACK2(wz1, wc.z); PACK2(wn1, wc.w);
        FMA_K(0, hl1, hh1, wr0, wz0, wn0);
        FMA_K(1, hl1, hh1, wr1, wz1, wn1);
    }
}

// Global W [g=300][k=100] -> smem W12 [kp][jp][12], slot = (k&1)*6 + (j&1)*3 + gate
__device__ __forceinline__ void load_weight12(const float* __restrict__ W,
                                              float* __restrict__ WtS, int tid)
{
    for (int idx = tid; idx < G3 * HID; idx += NTH) {
        int g = idx / HID;
        int k = idx - g * HID;
        int gate = g / HID;
        int j    = g - gate * HID;
        WtS[(k >> 1) * 600 + (j >> 1) * 12 + (k & 1) * 6 + (j & 1) * 3 + gate] = W[idx];
    }
}

__device__ __forceinline__ float gru_cell(float gi_r, float gi_z, float gi_n,
                                          float gr, float gz, float gn, float hold)
{
    float r = sigf(gi_r + gr);
    float z = sigf(gi_z + gz);
    float n = tanhf_(gi_n + r * gn);
    return (1.f - z) * n + z * hold;
}

// unpack one j's 12 accumulators into 8 floats per gate
#define UNPACK_J(jj, R, Z, N, acc) \
    UNPACK2(R[0], R[1], acc[AIX(jj,0,0)]); UNPACK2(R[2], R[3], acc[AIX(jj,0,1)]); \
    UNPACK2(R[4], R[5], acc[AIX(jj,0,2)]); UNPACK2(R[6], R[7], acc[AIX(jj,0,3)]); \
    UNPACK2(Z[0], Z[1], acc[AIX(jj,1,0)]); UNPACK2(Z[2], Z[3], acc[AIX(jj,1,1)]); \
    UNPACK2(Z[4], Z[5], acc[AIX(jj,1,2)]); UNPACK2(Z[6], Z[7], acc[AIX(jj,1,3)]); \
    UNPACK2(N[0], N[1], acc[AIX(jj,2,0)]); UNPACK2(N[2], N[3], acc[AIX(jj,2,1)]); \
    UNPACK2(N[4], N[5], acc[AIX(jj,2,2)]); UNPACK2(N[6], N[7], acc[AIX(jj,2,3)])

// ---------------- init: VBUF[s][b] = x[b][s] ----------------
__global__ void k_init(const float* __restrict__ x, int B)
{
    int idx = blockIdx.x * blockDim.x + threadIdx.x;
    if (idx < B * T) {
        int b = idx / T, s = idx - b * T;
        g_VBUF[s * B + b] = x[idx];
    }
}

// ---------------- K1: layer-0 recurrence ----------------
__global__ void __launch_bounds__(NTH, 1)
k_layer0(const float* __restrict__ Whh0, const float* __restrict__ Wih0,
         const float* __restrict__ bih0, const float* __restrict__ bhh0,
         int iter, int B)
{
    extern __shared__ float sm[];
    float* WtS  = sm + OFF_W;
    float* auxS = sm + OFF_A;   // [0:300) wih, [304:604) bih, [608:908) bhh

    const int tid = threadIdx.x;
    const int jp  = tid >> 3;
    const int bg  = tid & 7;
    const int bg0 = blockIdx.x * BT;
    const int j0  = 2 * jp, j1 = 2 * jp + 1;

    load_weight12(Whh0, WtS, tid);
    for (int idx = tid; idx < G3; idx += NTH) {
        auxS[idx]       = Wih0[idx];
        auxS[304 + idx] = bih0[idx];
        auxS[608 + idx] = bhh0[idx];
    }
    for (int idx = tid; idx < HID * BT; idx += NTH) sm[OFF_H0 + idx] = 0.f;
    __syncthreads();

    const float wir0 = auxS[j0],       wiz0 = auxS[100 + j0], win0 = auxS[200 + j0];
    const float wir1 = auxS[j1],       wiz1 = auxS[100 + j1], win1 = auxS[200 + j1];
    const float bir0 = auxS[304 + j0], biz0 = auxS[404 + j0], bin0 = auxS[504 + j0];
    const float bir1 = auxS[304 + j1], biz1 = auxS[404 + j1], bin1 = auxS[504 + j1];
    const float bhr0 = auxS[608 + j0], bhz0 = auxS[708 + j0], bhn0 = auxS[808 + j0];
    const float bhr1 = auxS[608 + j1], bhz1 = auxS[708 + j1], bhn1 = auxS[808 + j1];

    for (int t = 0; t < T; ++t) {
        float* hcur  = sm + ((t & 1) ? OFF_H1 : OFF_H0);
        float* hnext = sm + ((t & 1) ? OFF_H0 : OFF_H1);

        // prefetch x before the long matvec (latency hidden)
        const float* xb = g_VBUF + (size_t)(iter + t) * B + bg0 + 4 * bg;
        float xv[8];
        *(float4*)(xv)     = *(const float4*)xb;
        *(float4*)(xv + 4) = *(const float4*)(xb + 32);

        unsigned long long acc[24];
        matvec2(WtS, hcur, jp, bg, acc);

        float h0o[8], h1o[8];
        *(float4*)(h0o)     = *(const float4*)(hcur + j0 * 64 + 4 * bg);
        *(float4*)(h0o + 4) = *(const float4*)(hcur + j0 * 64 + 32 + 4 * bg);
        *(float4*)(h1o)     = *(const float4*)(hcur + j1 * 64 + 4 * bg);
        *(float4*)(h1o + 4) = *(const float4*)(hcur + j1 * 64 + 32 + 4 * bg);

        float R[8], Z[8], N[8], hn0[8], hn1[8];
        UNPACK_J(0, R, Z, N, acc);
        #pragma unroll
        for (int i = 0; i < 8; ++i)
            hn0[i] = gru_cell(xv[i]*wir0 + bir0, xv[i]*wiz0 + biz0, xv[i]*win0 + bin0,
                              R[i] + bhr0, Z[i] + bhz0, N[i] + bhn0, h0o[i]);
        UNPACK_J(1, R, Z, N, acc);
        #pragma unroll
        for (int i = 0; i < 8; ++i)
            hn1[i] = gru_cell(xv[i]*wir1 + bir1, xv[i]*wiz1 + biz1, xv[i]*win1 + bin1,
                              R[i] + bhr1, Z[i] + bhz1, N[i] + bhn1, h1o[i]);

        // write to the OTHER buffer: no read/write hazard with this t's matvec
        *(float4*)(hnext + j0 * 64 + 4 * bg)      = *(float4*)(hn0);
        *(float4*)(hnext + j0 * 64 + 32 + 4 * bg) = *(float4*)(hn0 + 4);
        *(float4*)(hnext + j1 * 64 + 4 * bg)      = *(float4*)(hn1);
        *(float4*)(hnext + j1 * 64 + 32 + 4 * bg) = *(float4*)(hn1 + 4);
        float* gw0 = g_H1 + (size_t)(t * HID + j0) * B + bg0 + 4 * bg;
        float* gw1 = g_H1 + (size_t)(t * HID + j1) * B + bg0 + 4 * bg;
        *(float4*)(gw0)      = *(float4*)(hn0);
        *(float4*)(gw0 + 32) = *(float4*)(hn0 + 4);
        *(float4*)(gw1)      = *(float4*)(hn1);
        *(float4*)(gw1 + 32) = *(float4*)(hn1 + 4);
        __syncthreads();       // single barrier per timestep
    }
}

// ---------------- K2: GI1[t] = Wih1 * H1[t] + b_ih1 (cp.async pipelined) ----------------
__device__ __forceinline__ void stage_h1(float* buf, int t, int bg0, int B, int tid)
{
    const float* gb = g_H1 + (size_t)t * HID * B + bg0;
    int s = tid * 16;
    #pragma unroll
    for (int q = 0; q < 4; ++q, s += 4)
        cp16(buf + s, gb + (size_t)(s >> 6) * B + (s & 63));
}

__global__ void __launch_bounds__(NTH, 1)
k_gi1(const float* __restrict__ Wih1, const float* __restrict__ bih1, int B)
{
    extern __shared__ float sm[];
    float* WtS  = sm + OFF_W;
    float* auxS = sm + OFF_A;

    const int tid = threadIdx.x;
    const int jp  = tid >> 3;
    const int bg  = tid & 7;
    const int bg0 = blockIdx.x * BT;
    const int j0  = 2 * jp, j1 = 2 * jp + 1;

    load_weight12(Wih1, WtS, tid);
    for (int idx = tid; idx < G3; idx += NTH) auxS[idx] = bih1[idx];

    stage_h1(sm + OFF_H0, 0, bg0, B, tid);   // prologue: tile 0
    CP_COMMIT();
    CP_WAIT0();
    __syncthreads();

    const float br0 = auxS[j0], bz0 = auxS[100 + j0], bn0 = auxS[200 + j0];
    const float br1 = auxS[j1], bz1 = auxS[100 + j1], bn1 = auxS[200 + j1];

    for (int t = 0; t < T; ++t) {
        float* hcur  = sm + ((t & 1) ? OFF_H1 : OFF_H0);
        float* hnext = sm + ((t & 1) ? OFF_H0 : OFF_H1);
        if (t + 1 < T) { stage_h1(hnext, t + 1, bg0, B, tid); CP_COMMIT(); }

        unsigned long long acc[24];
        matvec2(WtS, hcur, jp, bg, acc);

        float R[8], Z[8], N[8];
        float* gbase = g_GI1 + (size_t)t * G3 * B + bg0 + 4 * bg;
        UNPACK_J(0, R, Z, N, acc);
        { float* p = gbase + (size_t)j0 * B;
          *(float4*)(p)      = make_float4(R[0]+br0, R[1]+br0, R[2]+br0, R[3]+br0);
          *(float4*)(p + 32) = make_float4(R[4]+br0, R[5]+br0, R[6]+br0, R[7]+br0);
          p = gbase + (size_t)(100 + j0) * B;
          *(float4*)(p)      = make_float4(Z[0]+bz0, Z[1]+bz0, Z[2]+bz0, Z[3]+bz0);
          *(float4*)(p + 32) = make_float4(Z[4]+bz0, Z[5]+bz0, Z[6]+bz0, Z[7]+bz0);
          p = gbase + (size_t)(200 + j0) * B;
          *(float4*)(p)      = make_float4(N[0]+bn0, N[1]+bn0, N[2]+bn0, N[3]+bn0);
          *(float4*)(p + 32) = make_float4(N[4]+bn0, N[5]+bn0, N[6]+bn0, N[7]+bn0); }
        UNPACK_J(1, R, Z, N, acc);
        { float* p = gbase + (size_t)j1 * B;
          *(float4*)(p)      = make_float4(R[0]+br1, R[1]+br1, R[2]+br1, R[3]+br1);
          *(float4*)(p + 32) = make_float4(R[4]+br1, R[5]+br1, R[6]+br1, R[7]+br1);
          p = gbase + (size_t)(100 + j1) * B;
          *(float4*)(p)      = make_float4(Z[0]+bz1, Z[1]+bz1, Z[2]+bz1, Z[3]+bz1);
          *(float4*)(p + 32) = make_float4(Z[4]+bz1, Z[5]+bz1, Z[6]+bz1, Z[7]+bz1);
          p = gbase + (size_t)(200 + j1) * B;
          *(float4*)(p)      = make_float4(N[0]+bn1, N[1]+bn1, N[2]+bn1, N[3]+bn1);
          *(float4*)(p + 32) = make_float4(N[4]+bn1, N[5]+bn1, N[6]+bn1, N[7]+bn1); }

        CP_WAIT0();
        __syncthreads();
    }
}

// ---------------- K3: layer-1 recurrence + final linear ----------------
__global__ void __launch_bounds__(NTH, 1)
k_layer1(const float* __restrict__ Whh1, const float* __restrict__ bhh1,
         const float* __restrict__ Wlin, const float* __restrict__ blin,
         float* __restrict__ out, int iter, int B)
{
    extern __shared__ float sm[];
    float* WtS  = sm + OFF_W;
    float* auxS = sm + OFF_A;   // [0:300) bhh, [304:404) wlin

    const int tid = threadIdx.x;
    const int jp  = tid >> 3;
    const int bg  = tid & 7;
    const int bg0 = blockIdx.x * BT;
    const int j0  = 2 * jp, j1 = 2 * jp + 1;

    load_weight12(Whh1, WtS, tid);
    for (int idx = tid; idx < G3; idx += NTH) auxS[idx] = bhh1[idx];
    for (int idx = tid; idx < HID; idx += NTH) auxS[304 + idx] = Wlin[idx];
    for (int idx = tid; idx < HID * BT; idx += NTH) sm[OFF_H0 + idx] = 0.f;
    __syncthreads();

    const float bhr0 = auxS[j0], bhz0 = auxS[100 + j0], bhn0 = auxS[200 + j0];
    const float bhr1 = auxS[j1], bhz1 = auxS[100 + j1], bhn1 = auxS[200 + j1];

    for (int t = 0; t < T; ++t) {
        float* hcur  = sm + ((t & 1) ? OFF_H1 : OFF_H0);
        float* hnext = sm + ((t & 1) ? OFF_H0 : OFF_H1);
        const float* gbase = g_GI1 + (size_t)t * G3 * B + bg0 + 4 * bg;

        // hoist j0's GI1 loads BEFORE matvec: DRAM latency hidden under 100-k FMA loop
        float gr0[8], gz0[8], gn0[8];
        *(float4*)(gr0)     = *(const float4*)(gbase + (size_t)j0 * B);
        *(float4*)(gr0 + 4) = *(const float4*)(gbase + (size_t)j0 * B + 32);
        *(float4*)(gz0)     = *(const float4*)(gbase + (size_t)(100 + j0) * B);
        *(float4*)(gz0 + 4) = *(const float4*)(gbase + (size_t)(100 + j0) * B + 32);
        *(float4*)(gn0)     = *(const float4*)(gbase + (size_t)(200 + j0) * B);
        *(float4*)(gn0 + 4) = *(const float4*)(gbase + (size_t)(200 + j0) * B + 32);

        unsigned long long acc[24];
        matvec2(WtS, hcur, jp, bg, acc);

        // issue j1's GI1 loads immediately (overlap j0's epilogue)
        float gr1[8], gz1[8], gn1[8];
        *(float4*)(gr1)     = *(const float4*)(gbase + (size_t)j1 * B);
        *(float4*)(gr1 + 4) = *(const float4*)(gbase + (size_t)j1 * B + 32);
        *(float4*)(gz1)     = *(const float4*)(gbase + (size_t)(100 + j1) * B);
        *(float4*)(gz1 + 4) = *(const float4*)(gbase + (size_t)(100 + j1) * B + 32);
        *(float4*)(gn1)     = *(const float4*)(gbase + (size_t)(200 + j1) * B);
        *(float4*)(gn1 + 4) = *(const float4*)(gbase + (size_t)(200 + j1) * B + 32);

        float hn0[8], hn1[8];
        {   float R[8], Z[8], N[8], ho[8];
            UNPACK_J(0, R, Z, N, acc);
            *(float4*)(ho)     = *(const float4*)(hcur + j0 * 64 + 4 * bg);
            *(float4*)(ho + 4) = *(const float4*)(hcur + j0 * 64 + 32 + 4 * bg);
            #pragma unroll
            for (int i = 0; i < 8; ++i)
                hn0[i] = gru_cell(gr0[i], gz0[i], gn0[i],
                                  R[i] + bhr0, Z[i] + bhz0, N[i] + bhn0, ho[i]);
        }
        {   float R[8], Z[8], N[8], ho[8];
            UNPACK_J(1, R, Z, N, acc);
            *(float4*)(ho)     = *(const float4*)(hcur + j1 * 64 + 4 * bg);
            *(float4*)(ho + 4) = *(const float4*)(hcur + j1 * 64 + 32 + 4 * bg);
            #pragma unroll
            for (int i = 0; i < 8; ++i)
                hn1[i] = gru_cell(gr1[i], gz1[i], gn1[i],
                                  R[i] + bhr1, Z[i] + bhz1, N[i] + bhn1, ho[i]);
        }

        *(float4*)(hnext + j0 * 64 + 4 * bg)      = *(float4*)(hn0);
        *(float4*)(hnext + j0 * 64 + 32 + 4 * bg) = *(float4*)(hn0 + 4);
        *(float4*)(hnext + j1 * 64 + 4 * bg)      = *(float4*)(hn1);
        *(float4*)(hnext + j1 * 64 + 32 + 4 * bg) = *(float4*)(hn1 + 4);
        __syncthreads();       // single barrier per timestep
    }

    // final h lives in buffer 0 (T even). ret = h2 @ W_lin^T + b_lin
    if (tid < BT) {
        float acc = blin[0];
        #pragma unroll 10
        for (int k = 0; k < HID; ++k) acc += sm[OFF_H0 + k * 64 + tid] * auxS[304 + k];
        g_VBUF[(size_t)(T + iter) * B + bg0 + tid] = acc;
        out[(bg0 + tid) * NB + iter] = acc;
    }
}

extern "C" void kernel_launch(void* const* d_in, const int* in_sizes, int n_in,
                              void* d_out, int out_size)
{
    const float* x    = (const float*)d_in[0];
    const float* Wih0 = (const float*)d_in[1];
    const float* Whh0 = (const float*)d_in[2];
    const float* bih0 = (const float*)d_in[3];
    const float* bhh0 = (const float*)d_in[4];
    const float* Wih1 = (const float*)d_in[5];
    const float* Whh1 = (const float*)d_in[6];
    const float* bih1 = (const float*)d_in[7];
    const float* bhh1 = (const float*)d_in[8];
    const float* Wlin = (const float*)d_in[9];
    const float* blin = (const float*)d_in[10];
    float* out = (float*)d_out;

    const int B = in_sizes[0] / T;              // 65536
    const int smem = SMEM_FLOATS * (int)sizeof(float);

    cudaFuncSetAttribute(k_layer0, cudaFuncAttributeMaxDynamicSharedMemorySize, smem);
    cudaFuncSetAttribute(k_gi1,    cudaFuncAttributeMaxDynamicSharedMemorySize, smem);
    cudaFuncSetAttribute(k_layer1, cudaFuncAttributeMaxDynamicSharedMemorySize, smem);

    k_init<<<(B * T + 511) / 512, 512>>>(x, B);

    const int nblk = B / BT;                    // 1024 CTAs, ~6.92 waves
    for (int i = 0; i < NB; ++i) {
        k_layer0<<<nblk, NTH, smem>>>(Whh0, Wih0, bih0, bhh0, i, B);
        k_gi1  <<<nblk, NTH, smem>>>(Wih1, bih1, B);
        k_layer1<<<nblk, NTH, smem>>>(Whh1, bhh1, Wlin, blin, out, i, B);
    }
}

// round 13
// speedup vs baseline: 1.8401x; 1.5663x over previous
#include <cuda_runtime.h>
#include <cuda_bf16.h>
#include <cstdint>

#define HID 100
#define T   10
#define NB  5
#define BT  64
#define NTH 256
#define B_MAX 65536

#define LDB 240            // bf16 row stride in bytes (120 elems)
#define GATE_ROWS 104      // padded W rows per gate block
#define KTILES 7           // k = 112 (100 real + 12 zero)

// SMEM byte layout
#define SM_WHI 0
#define SM_WLO 74880       // 312 * 240
#define SM_H   149760      // 4 h buffers: [hi0, lo0, hi1, lo1], each 64*240
#define HBUF   15360
#define SM_AUX 211200      // 1024 floats aux
#define SMEM_BYTES 215296

// Scratch (static device memory; kernel_launch stays allocation-free)
__device__ float g_VBUF[(T + NB) * B_MAX];
__device__ float g_H1[T * HID * B_MAX];
__device__ float g_GI1[T * 3 * HID * B_MAX];

__device__ __forceinline__ float sigf(float x)   { return __fdividef(1.f, 1.f + __expf(-x)); }
__device__ __forceinline__ float tanhf_(float x) { return 1.f - __fdividef(2.f, __expf(2.f * x) + 1.f); }

__device__ __forceinline__ uint32_t sm32(const void* p) {
    return (uint32_t)__cvta_generic_to_shared(p);
}

__device__ __forceinline__ void ldsm_x4(uint32_t* r, uint32_t a) {
    asm volatile("ldmatrix.sync.aligned.m8n8.x4.shared.b16 {%0,%1,%2,%3}, [%4];"
        : "=r"(r[0]), "=r"(r[1]), "=r"(r[2]), "=r"(r[3]) : "r"(a));
}
__device__ __forceinline__ void ldsm_x2(uint32_t* r, uint32_t a) {
    asm volatile("ldmatrix.sync.aligned.m8n8.x2.shared.b16 {%0,%1}, [%2];"
        : "=r"(r[0]), "=r"(r[1]) : "r"(a));
}
__device__ __forceinline__ void mma_bf16(float* c, const uint32_t* a, const uint32_t* b) {
    asm volatile(
        "mma.sync.aligned.m16n8k16.row.col.f32.bf16.bf16.f32 "
        "{%0,%1,%2,%3}, {%4,%5,%6,%7}, {%8,%9}, {%0,%1,%2,%3};"
        : "+f"(c[0]), "+f"(c[1]), "+f"(c[2]), "+f"(c[3])
        : "r"(a[0]), "r"(a[1]), "r"(a[2]), "r"(a[3]), "r"(b[0]), "r"(b[1]));
}

__device__ __forceinline__ uint32_t pack_bf2(float a, float b) {
    __nv_bfloat162 v = __halves2bfloat162(__float2bfloat16(a), __float2bfloat16(b));
    return *reinterpret_cast<uint32_t*>(&v);
}
// pack fp32 pair into hi word + residual-lo word
__device__ __forceinline__ void pack_hilo(float a, float b, uint32_t& hi, uint32_t& lo) {
    __nv_bfloat16 ha = __float2bfloat16(a), hb = __float2bfloat16(b);
    hi = pack_bf2(__bfloat162float(ha), __bfloat162float(hb));
    // reuse exact hi halves:
    __nv_bfloat162 vh = *reinterpret_cast<__nv_bfloat162*>(&hi);
    lo = pack_bf2(a - __bfloat162float(vh.x), b - __bfloat162float(vh.y));
}

// D[b=64][g=384] = h[64][112] * W^T : acc[mt 4][gate*2+d 6][c 4]
// c0=(b0,j0) c1=(b0,j1) c2=(b1,j0) c3=(b1,j1); b0=16mt+l/4, b1=b0+8; j0=16w+8d+2(l&3)
__device__ __forceinline__ void mma_all(uint32_t whi, uint32_t wlo,
                                        uint32_t hhi, uint32_t hlo,
                                        int w, int l, int nd, float acc[4][6][4])
{
    #pragma unroll
    for (int i = 0; i < 4; ++i)
        #pragma unroll
        for (int j = 0; j < 6; ++j)
            #pragma unroll
            for (int k = 0; k < 4; ++k) acc[i][j][k] = 0.f;
    if (nd == 0) return;

    const uint32_t a_hi = hhi + (l & 15) * LDB + ((l >> 4) << 4);
    const uint32_t a_lo = hlo + (l & 15) * LDB + ((l >> 4) << 4);
    const uint32_t brow = (l & 7) * LDB + (((l >> 3) & 1) << 4);

    #pragma unroll
    for (int kt = 0; kt < KTILES; ++kt) {
        uint32_t ah[4][4], al[4][4];
        #pragma unroll
        for (int mt = 0; mt < 4; ++mt) {
            ldsm_x4(ah[mt], a_hi + mt * 16 * LDB + kt * 32);
            ldsm_x4(al[mt], a_lo + mt * 16 * LDB + kt * 32);
        }
        #pragma unroll
        for (int g = 0; g < 3; ++g) {
            #pragma unroll
            for (int d = 0; d < 2; ++d) {
                if (d < nd) {
                    uint32_t off = (g * GATE_ROWS + 16 * w + 8 * d) * LDB + kt * 32 + brow;
                    uint32_t bh[2], bl[2];
                    ldsm_x2(bh, whi + off);
                    ldsm_x2(bl, wlo + off);
                    #pragma unroll
                    for (int mt = 0; mt < 4; ++mt) {
                        mma_bf16(acc[mt][g * 2 + d], ah[mt], bh);
                        mma_bf16(acc[mt][g * 2 + d], al[mt], bh);
                        mma_bf16(acc[mt][g * 2 + d], ah[mt], bl);
                    }
                }
            }
        }
    }
}

// W [300][100] fp32 -> smem bf16 hi/lo tiles [gate*104 + j][k], zero-padded
__device__ void setup_W(const float* __restrict__ W, char* smc, int tid)
{
    float4 z4 = make_float4(0.f, 0.f, 0.f, 0.f);
    for (int i = tid; i < (SM_H - SM_WHI) / 16; i += NTH) ((float4*)(smc + SM_WHI))[i] = z4;
    for (int i = tid; i < 4 * HBUF / 16; i += NTH)        ((float4*)(smc + SM_H))[i]   = z4;
    __syncthreads();
    for (int idx = tid; idx < 3 * HID * HID; idx += NTH) {
        int g = idx / HID, k = idx - g * HID;
        int gate = g / HID, j = g - gate * HID;
        float v = W[idx];
        __nv_bfloat16 hi = __float2bfloat16(v);
        __nv_bfloat16 lo = __float2bfloat16(v - __bfloat162float(hi));
        uint32_t off = (uint32_t)(gate * GATE_ROWS + j) * LDB + k * 2;
        *(__nv_bfloat16*)(smc + SM_WHI + off) = hi;
        *(__nv_bfloat16*)(smc + SM_WLO + off) = lo;
    }
}

// ---------------- init: VBUF[s][b] = x[b][s] ----------------
__global__ void k_init(const float* __restrict__ x, int B)
{
    int idx = blockIdx.x * blockDim.x + threadIdx.x;
    if (idx < B * T) {
        int b = idx / T, s = idx - b * T;
        g_VBUF[s * B + b] = x[idx];
    }
}

// ---------------- K1: layer-0 recurrence ----------------
__global__ void __launch_bounds__(NTH, 1)
k_layer0(const float* __restrict__ Whh0, const float* __restrict__ Wih0,
         const float* __restrict__ bih0, const float* __restrict__ bhh0,
         int iter, int B)
{
    extern __shared__ char smc[];
    float* aux = (float*)(smc + SM_AUX);   // [0:300) wih, [304:604) bih, [608:908) bhh
    const int tid = threadIdx.x, w = tid >> 5, l = tid & 31;
    const int bg0 = blockIdx.x * BT;
    const int nd = (16 * w < 100) ? ((16 * w + 8 < 100) ? 2 : 1) : 0;
    const uint32_t whi = sm32(smc + SM_WHI), wlo = sm32(smc + SM_WLO);

    setup_W(Whh0, smc, tid);
    for (int i = tid; i < 300; i += NTH) {
        aux[i] = Wih0[i]; aux[304 + i] = bih0[i]; aux[608 + i] = bhh0[i];
    }
    __syncthreads();

    float hold[4][2][4];
    #pragma unroll
    for (int a = 0; a < 4; ++a)
        #pragma unroll
        for (int b = 0; b < 2; ++b)
            #pragma unroll
            for (int c = 0; c < 4; ++c) hold[a][b][c] = 0.f;

    for (int t = 0; t < T; ++t) {
        char* hc = smc + SM_H + (t & 1) * 2 * HBUF;
        char* hn = smc + SM_H + ((t + 1) & 1) * 2 * HBUF;
        float acc[4][6][4];
        mma_all(whi, wlo, sm32(hc), sm32(hc + HBUF), w, l, nd, acc);

        const float* xr = g_VBUF + (size_t)(iter + t) * B + bg0;
        #pragma unroll
        for (int mt = 0; mt < 4; ++mt) {
            int b0 = 16 * mt + (l >> 2), b1 = b0 + 8;
            float x0 = xr[b0], x1 = xr[b1];
            #pragma unroll
            for (int d = 0; d < 2; ++d) {
                if (d < nd) {
                    int j0 = 16 * w + 8 * d + 2 * (l & 3);
                    if (j0 < 100) {
                        float2 wr = *(float2*)(aux + j0),       wz = *(float2*)(aux + 100 + j0),       wn = *(float2*)(aux + 200 + j0);
                        float2 br = *(float2*)(aux + 304 + j0), bz = *(float2*)(aux + 404 + j0),       bn = *(float2*)(aux + 504 + j0);
                        float2 hr = *(float2*)(aux + 608 + j0), hz = *(float2*)(aux + 708 + j0),       hn2 = *(float2*)(aux + 808 + j0);
                        float* ar = acc[mt][0 + d]; float* az = acc[mt][2 + d]; float* an = acc[mt][4 + d];
                        float h[4];
                        #pragma unroll
                        for (int c = 0; c < 4; ++c) {
                            float xv = (c < 2) ? x0 : x1;
                            float wrc = (c & 1) ? wr.y : wr.x, wzc = (c & 1) ? wz.y : wz.x, wnc = (c & 1) ? wn.y : wn.x;
                            float brc = (c & 1) ? br.y : br.x, bzc = (c & 1) ? bz.y : bz.x, bnc = (c & 1) ? bn.y : bn.x;
                            float hrc = (c & 1) ? hr.y : hr.x, hzc = (c & 1) ? hz.y : hz.x, hnc = (c & 1) ? hn2.y : hn2.x;
                            float r = sigf(xv * wrc + brc + ar[c] + hrc);
                            float z = sigf(xv * wzc + bzc + az[c] + hzc);
                            float n = tanhf_(xv * wnc + bnc + r * (an[c] + hnc));
                            h[c] = (1.f - z) * n + z * hold[mt][d][c];
                            hold[mt][d][c] = h[c];
                        }
                        uint32_t hi0, lo0, hi1, lo1;
                        pack_hilo(h[0], h[1], hi0, lo0);
                        pack_hilo(h[2], h[3], hi1, lo1);
                        *(uint32_t*)(hn + b0 * LDB + j0 * 2)        = hi0;
                        *(uint32_t*)(hn + HBUF + b0 * LDB + j0 * 2) = lo0;
                        *(uint32_t*)(hn + b1 * LDB + j0 * 2)        = hi1;
                        *(uint32_t*)(hn + HBUF + b1 * LDB + j0 * 2) = lo1;
                        float* gb = g_H1 + ((size_t)t * HID + j0) * B + bg0;
                        gb[b0] = h[0]; gb[B + b0] = h[1];
                        gb[b1] = h[2]; gb[B + b1] = h[3];
                    }
                }
            }
        }
        __syncthreads();
    }
}

// ---------------- K2: GI1[t] = Wih1 * H1[t] + b_ih1 ----------------
__device__ __forceinline__ void stage_h(char* hhi, char* hlo, int t, int bg0, int B, int tid)
{
    for (int idx = tid; idx < 3200; idx += NTH) {
        int j = (idx >> 6) * 2, b = idx & 63;
        const float* gb = g_H1 + ((size_t)t * HID + j) * B + bg0 + b;
        float v0 = gb[0], v1 = gb[B];
        uint32_t hi, lo;
        pack_hilo(v0, v1, hi, lo);
        *(uint32_t*)(hhi + b * LDB + j * 2) = hi;
        *(uint32_t*)(hlo + b * LDB + j * 2) = lo;
    }
}

__global__ void __launch_bounds__(NTH, 1)
k_gi1(const float* __restrict__ Wih1, const float* __restrict__ bih1, int B)
{
    extern __shared__ char smc[];
    float* aux = (float*)(smc + SM_AUX);
    const int tid = threadIdx.x, w = tid >> 5, l = tid & 31;
    const int bg0 = blockIdx.x * BT;
    const int nd = (16 * w < 100) ? ((16 * w + 8 < 100) ? 2 : 1) : 0;
    const uint32_t whi = sm32(smc + SM_WHI), wlo = sm32(smc + SM_WLO);

    setup_W(Wih1, smc, tid);
    for (int i = tid; i < 300; i += NTH) aux[i] = bih1[i];
    __syncthreads();
    stage_h(smc + SM_H, smc + SM_H + HBUF, 0, bg0, B, tid);
    __syncthreads();

    for (int t = 0; t < T; ++t) {
        char* hc = smc + SM_H + (t & 1) * 2 * HBUF;
        char* hn = smc + SM_H + ((t + 1) & 1) * 2 * HBUF;
        float acc[4][6][4];
        mma_all(whi, wlo, sm32(hc), sm32(hc + HBUF), w, l, nd, acc);

        if (t + 1 < T) stage_h(hn, hn + HBUF, t + 1, bg0, B, tid);

        float* gt = g_GI1 + (size_t)t * 3 * HID * B + bg0;
        #pragma unroll
        for (int mt = 0; mt < 4; ++mt) {
            int b0 = 16 * mt + (l >> 2), b1 = b0 + 8;
            #pragma unroll
            for (int d = 0; d < 2; ++d) {
                if (d < nd) {
                    int j0 = 16 * w + 8 * d + 2 * (l & 3);
                    if (j0 < 100) {
                        float2 br = *(float2*)(aux + j0), bz = *(float2*)(aux + 100 + j0), bn = *(float2*)(aux + 200 + j0);
                        #pragma unroll
                        for (int g = 0; g < 3; ++g) {
                            float* a = acc[mt][g * 2 + d];
                            float2 bs = (g == 0) ? br : ((g == 1) ? bz : bn);
                            float* p = gt + ((size_t)g * HID + j0) * B;
                            p[b0]     = a[0] + bs.x;
                            p[B + b0] = a[1] + bs.y;
                            p[b1]     = a[2] + bs.x;
                            p[B + b1] = a[3] + bs.y;
                        }
                    }
                }
            }
        }
        __syncthreads();
    }
}

// ---------------- K3: layer-1 recurrence + final linear ----------------
__device__ __forceinline__ void load_gi(float* gi, const float* gt, int B, int j0, int b0)
{
    int js = (j0 < 100) ? j0 : 0;
    int b1 = b0 + 8;
    #pragma unroll
    for (int g = 0; g < 3; ++g) {
        const float* p = gt + ((size_t)g * HID + js) * B;
        gi[g * 4 + 0] = p[b0];
        gi[g * 4 + 1] = p[B + b0];
        gi[g * 4 + 2] = p[b1];
        gi[g * 4 + 3] = p[B + b1];
    }
}

__global__ void __launch_bounds__(NTH, 1)
k_layer1(const float* __restrict__ Whh1, const float* __restrict__ bhh1,
         const float* __restrict__ Wlin, const float* __restrict__ blin,
         float* __restrict__ out, int iter, int B)
{
    extern __shared__ char smc[];
    float* aux = (float*)(smc + SM_AUX);   // [0:300) bhh, [304:404) wlin
    const int tid = threadIdx.x, w = tid >> 5, l = tid & 31;
    const int bg0 = blockIdx.x * BT;
    const int nd = (16 * w < 100) ? ((16 * w + 8 < 100) ? 2 : 1) : 0;
    const uint32_t whi = sm32(smc + SM_WHI), wlo = sm32(smc + SM_WLO);

    setup_W(Whh1, smc, tid);
    for (int i = tid; i < 300; i += NTH) aux[i] = bhh1[i];
    for (int i = tid; i < HID; i += NTH)  aux[304 + i] = Wlin[i];
    __syncthreads();

    float hold[4][2][4];
    #pragma unroll
    for (int a = 0; a < 4; ++a)
        #pragma unroll
        for (int b = 0; b < 2; ++b)
            #pragma unroll
            for (int c = 0; c < 4; ++c) hold[a][b][c] = 0.f;

    const int step = (nd == 2) ? 1 : 2;
    for (int t = 0; t < T; ++t) {
        char* hc = smc + SM_H + (t & 1) * 2 * HBUF;
        char* hn = smc + SM_H + ((t + 1) & 1) * 2 * HBUF;
        const float* gt = g_GI1 + (size_t)t * 3 * HID * B + bg0;

        float gi[12] = {0};
        if (nd > 0) load_gi(gi, gt, B, 16 * w + 2 * (l & 3), l >> 2);   // chunk (mt0,d0)

        float acc[4][6][4];
        mma_all(whi, wlo, sm32(hc), sm32(hc + HBUF), w, l, nd, acc);

        #pragma unroll
        for (int ci = 0; ci < 8; ++ci) {
            int mt = ci >> 1, d = ci & 1;
            if (d < nd) {
                // prefetch next valid chunk
                float gin[12] = {0};
                int nx = ci + step;
                if (nx < 8) {
                    int nmt = nx >> 1, ndd = nx & 1;
                    load_gi(gin, gt, B, 16 * w + 8 * ndd + 2 * (l & 3), 16 * nmt + (l >> 2));
                }
                int j0 = 16 * w + 8 * d + 2 * (l & 3);
                int b0 = 16 * mt + (l >> 2), b1 = b0 + 8;
                bool jv = j0 < 100;
                int js = jv ? j0 : 0;
                float2 hr = *(float2*)(aux + js), hz = *(float2*)(aux + 100 + js), hn2 = *(float2*)(aux + 200 + js);
                float* ar = acc[mt][0 + d]; float* az = acc[mt][2 + d]; float* an = acc[mt][4 + d];
                float h[4];
                #pragma unroll
                for (int c = 0; c < 4; ++c) {
                    float hrc = (c & 1) ? hr.y : hr.x, hzc = (c & 1) ? hz.y : hz.x, hnc = (c & 1) ? hn2.y : hn2.x;
                    float r = sigf(gi[0 + c] + ar[c] + hrc);
                    float z = sigf(gi[4 + c] + az[c] + hzc);
                    float n = tanhf_(gi[8 + c] + r * (an[c] + hnc));
                    h[c] = (1.f - z) * n + z * hold[mt][d][c];
                    hold[mt][d][c] = h[c];
                }
                if (jv) {
                    uint32_t hi0, lo0, hi1, lo1;
                    pack_hilo(h[0], h[1], hi0, lo0);
                    pack_hilo(h[2], h[3], hi1, lo1);
                    *(uint32_t*)(hn + b0 * LDB + j0 * 2)        = hi0;
                    *(uint32_t*)(hn + HBUF + b0 * LDB + j0 * 2) = lo0;
                    *(uint32_t*)(hn + b1 * LDB + j0 * 2)        = hi1;
                    *(uint32_t*)(hn + HBUF + b1 * LDB + j0 * 2) = lo1;
                }
                #pragma unroll
                for (int q = 0; q < 12; ++q) gi[q] = gin[q];
            }
        }
        __syncthreads();
    }

    // dump fp32 h to scratch (reuse W region), reduce with W_lin
    float* scr = (float*)(smc + SM_WHI);   // [j][b], 100*64 floats
    #pragma unroll
    for (int mt = 0; mt < 4; ++mt) {
        int b0 = 16 * mt + (l >> 2), b1 = b0 + 8;
        #pragma unroll
        for (int d = 0; d < 2; ++d) {
            if (d < nd) {
                int j0 = 16 * w + 8 * d + 2 * (l & 3);
                if (j0 < 100) {
                    scr[j0 * 64 + b0]       = hold[mt][d][0];
                    scr[(j0 + 1) * 64 + b0] = hold[mt][d][1];
                    scr[j0 * 64 + b1]       = hold[mt][d][2];
                    scr[(j0 + 1) * 64 + b1] = hold[mt][d][3];
                }
            }
        }
    }
    __syncthreads();
    if (tid < BT) {
        float acc = blin[0];
        #pragma unroll 10
        for (int k = 0; k < HID; ++k) acc += scr[k * 64 + tid] * aux[304 + k];
        g_VBUF[(size_t)(T + iter) * B + bg0 + tid] = acc;
        out[(bg0 + tid) * NB + iter] = acc;
    }
}

extern "C" void kernel_launch(void* const* d_in, const int* in_sizes, int n_in,
                              void* d_out, int out_size)
{
    const float* x    = (const float*)d_in[0];
    const float* Wih0 = (const float*)d_in[1];
    const float* Whh0 = (const float*)d_in[2];
    const float* bih0 = (const float*)d_in[3];
    const float* bhh0 = (const float*)d_in[4];
    const float* Wih1 = (const float*)d_in[5];
    const float* Whh1 = (const float*)d_in[6];
    const float* bih1 = (const float*)d_in[7];
    const float* bhh1 = (const float*)d_in[8];
    const float* Wlin = (const float*)d_in[9];
    const float* blin = (const float*)d_in[10];
    float* out = (float*)d_out;

    const int B = in_sizes[0] / T;              // 65536

    cudaFuncSetAttribute(k_layer0, cudaFuncAttributeMaxDynamicSharedMemorySize, SMEM_BYTES);
    cudaFuncSetAttribute(k_gi1,    cudaFuncAttributeMaxDynamicSharedMemorySize, SMEM_BYTES);
    cudaFuncSetAttribute(k_layer1, cudaFuncAttributeMaxDynamicSharedMemorySize, SMEM_BYTES);

    k_init<<<(B * T + 511) / 512, 512>>>(x, B);

    const int nblk = B / BT;                    // 1024 CTAs
    for (int i = 0; i < NB; ++i) {
        k_layer0<<<nblk, NTH, SMEM_BYTES>>>(Whh0, Wih0, bih0, bhh0, i, B);
        k_gi1  <<<nblk, NTH, SMEM_BYTES>>>(Wih1, bih1, B);
        k_layer1<<<nblk, NTH, SMEM_BYTES>>>(Whh1, bhh1, Wlin, blin, out, i, B);
    }
}

// round 14
// speedup vs baseline: 2.0440x; 1.1108x over previous
#include <cuda_runtime.h>
#include <cuda_bf16.h>
#include <cstdint>

#define HID 100
#define T   10
#define NB  5
#define BT  64
#define NTH 512
#define B_MAX 65536

#define LDB 240            // bf16 row stride in bytes (120 elems)
#define GATE_ROWS 104      // padded W rows per gate block
#define KTILES 7           // k = 112 (100 real + 12 zero)

// SMEM byte layout
#define SM_WHI 0
#define SM_WLO 74880       // 312 * 240
#define SM_H   149760      // 4 h buffers: [hi0, lo0, hi1, lo1], each 64*240
#define HBUF   15360
#define SM_AUX 211200      // 1024 floats aux
#define SMEM_BYTES 215296

// Scratch (static device memory; kernel_launch stays allocation-free)
__device__ float g_VBUF[(T + NB) * B_MAX];
__device__ float g_H1[T * HID * B_MAX];
__device__ float g_GI1[T * 3 * HID * B_MAX];

__device__ __forceinline__ float sigf(float x)   { return __fdividef(1.f, 1.f + __expf(-x)); }
__device__ __forceinline__ float tanhf_(float x) { return 1.f - __fdividef(2.f, __expf(2.f * x) + 1.f); }

__device__ __forceinline__ uint32_t sm32(const void* p) {
    return (uint32_t)__cvta_generic_to_shared(p);
}

__device__ __forceinline__ void ldsm_x4(uint32_t* r, uint32_t a) {
    asm volatile("ldmatrix.sync.aligned.m8n8.x4.shared.b16 {%0,%1,%2,%3}, [%4];"
        : "=r"(r[0]), "=r"(r[1]), "=r"(r[2]), "=r"(r[3]) : "r"(a));
}
__device__ __forceinline__ void ldsm_x2(uint32_t* r, uint32_t a) {
    asm volatile("ldmatrix.sync.aligned.m8n8.x2.shared.b16 {%0,%1}, [%2];"
        : "=r"(r[0]), "=r"(r[1]) : "r"(a));
}
__device__ __forceinline__ void mma_bf16(float* c, const uint32_t* a, const uint32_t* b) {
    asm volatile(
        "mma.sync.aligned.m16n8k16.row.col.f32.bf16.bf16.f32 "
        "{%0,%1,%2,%3}, {%4,%5,%6,%7}, {%8,%9}, {%0,%1,%2,%3};"
        : "+f"(c[0]), "+f"(c[1]), "+f"(c[2]), "+f"(c[3])
        : "r"(a[0]), "r"(a[1]), "r"(a[2]), "r"(a[3]), "r"(b[0]), "r"(b[1]));
}

__device__ __forceinline__ uint32_t pack_bf2(float a, float b) {
    __nv_bfloat162 v = __halves2bfloat162(__float2bfloat16(a), __float2bfloat16(b));
    return *reinterpret_cast<uint32_t*>(&v);
}
__device__ __forceinline__ void pack_hilo(float a, float b, uint32_t& hi, uint32_t& lo) {
    __nv_bfloat16 ha = __float2bfloat16(a), hb = __float2bfloat16(b);
    hi = pack_bf2(__bfloat162float(ha), __bfloat162float(hb));
    __nv_bfloat162 vh = *reinterpret_cast<__nv_bfloat162*>(&hi);
    lo = pack_bf2(a - __bfloat162float(vh.x), b - __bfloat162float(vh.y));
}

// 16 warps = (2 mw) x (8 jw). Warp computes M-tiles mt = {2mw, 2mw+1} (32 batches)
// x its j-slots: j0 = 16jw + 8d + 2(l&3), d < nd.
// acc[mt_i 2][gate*2+d 6][c 4]; c: (b0,j0)(b0,j1)(b1,j0)(b1,j1), b0=16mt+l/4, b1=b0+8
__device__ __forceinline__ void mma_all(uint32_t whi, uint32_t wlo,
                                        uint32_t hhi, uint32_t hlo,
                                        int jw, int mw, int l, int nd,
                                        float acc[2][6][4])
{
    #pragma unroll
    for (int i = 0; i < 2; ++i)
        #pragma unroll
        for (int j = 0; j < 6; ++j)
            #pragma unroll
            for (int k = 0; k < 4; ++k) acc[i][j][k] = 0.f;
    if (nd == 0) return;

    const uint32_t a_hi = hhi + (l & 15) * LDB + ((l >> 4) << 4) + 2 * mw * 16 * LDB;
    const uint32_t a_lo = hlo + (l & 15) * LDB + ((l >> 4) << 4) + 2 * mw * 16 * LDB;
    const uint32_t brow = (l & 7) * LDB + (((l >> 3) & 1) << 4);

    #pragma unroll
    for (int kt = 0; kt < KTILES; ++kt) {
        uint32_t ah[2][4], al[2][4];
        #pragma unroll
        for (int i = 0; i < 2; ++i) {
            ldsm_x4(ah[i], a_hi + i * 16 * LDB + kt * 32);
            ldsm_x4(al[i], a_lo + i * 16 * LDB + kt * 32);
        }
        #pragma unroll
        for (int g = 0; g < 3; ++g) {
            #pragma unroll
            for (int d = 0; d < 2; ++d) {
                if (d < nd) {
                    uint32_t off = (g * GATE_ROWS + 16 * jw + 8 * d) * LDB + kt * 32 + brow;
                    uint32_t bh[2], bl[2];
                    ldsm_x2(bh, whi + off);
                    ldsm_x2(bl, wlo + off);
                    #pragma unroll
                    for (int i = 0; i < 2; ++i) {
                        mma_bf16(acc[i][g * 2 + d], ah[i], bh);
                        mma_bf16(acc[i][g * 2 + d], al[i], bh);
                        mma_bf16(acc[i][g * 2 + d], ah[i], bl);
                    }
                }
            }
        }
    }
}

// W [300][100] fp32 -> smem bf16 hi/lo tiles [gate*104 + j][k], zero-padded
__device__ void setup_W(const float* __restrict__ W, char* smc, int tid)
{
    float4 z4 = make_float4(0.f, 0.f, 0.f, 0.f);
    for (int i = tid; i < (SM_H - SM_WHI) / 16; i += NTH) ((float4*)(smc + SM_WHI))[i] = z4;
    for (int i = tid; i < 4 * HBUF / 16; i += NTH)        ((float4*)(smc + SM_H))[i]   = z4;
    __syncthreads();
    for (int idx = tid; idx < 3 * HID * HID; idx += NTH) {
        int g = idx / HID, k = idx - g * HID;
        int gate = g / HID, j = g - gate * HID;
        float v = W[idx];
        __nv_bfloat16 hi = __float2bfloat16(v);
        __nv_bfloat16 lo = __float2bfloat16(v - __bfloat162float(hi));
        uint32_t off = (uint32_t)(gate * GATE_ROWS + j) * LDB + k * 2;
        *(__nv_bfloat16*)(smc + SM_WHI + off) = hi;
        *(__nv_bfloat16*)(smc + SM_WLO + off) = lo;
    }
}

// ---------------- init: VBUF[s][b] = x[b][s] ----------------
__global__ void k_init(const float* __restrict__ x, int B)
{
    int idx = blockIdx.x * blockDim.x + threadIdx.x;
    if (idx < B * T) {
        int b = idx / T, s = idx - b * T;
        g_VBUF[s * B + b] = x[idx];
    }
}

// ---------------- K1: layer-0 recurrence ----------------
__global__ void __launch_bounds__(NTH, 1)
k_layer0(const float* __restrict__ Whh0, const float* __restrict__ Wih0,
         const float* __restrict__ bih0, const float* __restrict__ bhh0,
         int iter, int B)
{
    extern __shared__ char smc[];
    float* aux = (float*)(smc + SM_AUX);   // [0:300) wih, [304:604) bih, [608:908) bhh
    const int tid = threadIdx.x, w = tid >> 5, l = tid & 31;
    const int mw = w & 1, jw = w >> 1;
    const int bg0 = blockIdx.x * BT;
    const int nd = (16 * jw < 100) ? ((16 * jw + 8 < 100) ? 2 : 1) : 0;
    const uint32_t whi = sm32(smc + SM_WHI), wlo = sm32(smc + SM_WLO);

    setup_W(Whh0, smc, tid);
    for (int i = tid; i < 300; i += NTH) {
        aux[i] = Wih0[i]; aux[304 + i] = bih0[i]; aux[608 + i] = bhh0[i];
    }
    __syncthreads();

    float hold[2][2][4];
    #pragma unroll
    for (int a = 0; a < 2; ++a)
        #pragma unroll
        for (int b = 0; b < 2; ++b)
            #pragma unroll
            for (int c = 0; c < 4; ++c) hold[a][b][c] = 0.f;

    for (int t = 0; t < T; ++t) {
        char* hc = smc + SM_H + (t & 1) * 2 * HBUF;
        char* hn = smc + SM_H + ((t + 1) & 1) * 2 * HBUF;
        float acc[2][6][4];
        mma_all(whi, wlo, sm32(hc), sm32(hc + HBUF), jw, mw, l, nd, acc);

        const float* xr = g_VBUF + (size_t)(iter + t) * B + bg0;
        #pragma unroll
        for (int i = 0; i < 2; ++i) {
            int mt = 2 * mw + i;
            int b0 = 16 * mt + (l >> 2), b1 = b0 + 8;
            float x0 = xr[b0], x1 = xr[b1];
            #pragma unroll
            for (int d = 0; d < 2; ++d) {
                if (d < nd) {
                    int j0 = 16 * jw + 8 * d + 2 * (l & 3);
                    if (j0 < 100) {
                        float2 wr = *(float2*)(aux + j0),       wz = *(float2*)(aux + 100 + j0),       wn = *(float2*)(aux + 200 + j0);
                        float2 br = *(float2*)(aux + 304 + j0), bz = *(float2*)(aux + 404 + j0),       bn = *(float2*)(aux + 504 + j0);
                        float2 hr = *(float2*)(aux + 608 + j0), hz = *(float2*)(aux + 708 + j0),       hn2 = *(float2*)(aux + 808 + j0);
                        float* ar = acc[i][0 + d]; float* az = acc[i][2 + d]; float* an = acc[i][4 + d];
                        float h[4];
                        #pragma unroll
                        for (int c = 0; c < 4; ++c) {
                            float xv = (c < 2) ? x0 : x1;
                            float wrc = (c & 1) ? wr.y : wr.x, wzc = (c & 1) ? wz.y : wz.x, wnc = (c & 1) ? wn.y : wn.x;
                            float brc = (c & 1) ? br.y : br.x, bzc = (c & 1) ? bz.y : bz.x, bnc = (c & 1) ? bn.y : bn.x;
                            float hrc = (c & 1) ? hr.y : hr.x, hzc = (c & 1) ? hz.y : hz.x, hnc = (c & 1) ? hn2.y : hn2.x;
                            float r = sigf(xv * wrc + brc + ar[c] + hrc);
                            float z = sigf(xv * wzc + bzc + az[c] + hzc);
                            float n = tanhf_(xv * wnc + bnc + r * (an[c] + hnc));
                            h[c] = (1.f - z) * n + z * hold[i][d][c];
                            hold[i][d][c] = h[c];
                        }
                        uint32_t hi0, lo0, hi1, lo1;
                        pack_hilo(h[0], h[1], hi0, lo0);
                        pack_hilo(h[2], h[3], hi1, lo1);
                        *(uint32_t*)(hn + b0 * LDB + j0 * 2)        = hi0;
                        *(uint32_t*)(hn + HBUF + b0 * LDB + j0 * 2) = lo0;
                        *(uint32_t*)(hn + b1 * LDB + j0 * 2)        = hi1;
                        *(uint32_t*)(hn + HBUF + b1 * LDB + j0 * 2) = lo1;
                        float* gb = g_H1 + ((size_t)t * HID + j0) * B + bg0;
                        gb[b0] = h[0]; gb[B + b0] = h[1];
                        gb[b1] = h[2]; gb[B + b1] = h[3];
                    }
                }
            }
        }
        __syncthreads();
    }
}

// ---------------- K2: GI1[t] = Wih1 * H1[t] + b_ih1 ----------------
__device__ __forceinline__ void stage_h(char* hhi, char* hlo, int t, int bg0, int B, int tid)
{
    for (int idx = tid; idx < 3200; idx += NTH) {
        int j = (idx >> 6) * 2, b = idx & 63;
        const float* gb = g_H1 + ((size_t)t * HID + j) * B + bg0 + b;
        float v0 = gb[0], v1 = gb[B];
        uint32_t hi, lo;
        pack_hilo(v0, v1, hi, lo);
        *(uint32_t*)(hhi + b * LDB + j * 2) = hi;
        *(uint32_t*)(hlo + b * LDB + j * 2) = lo;
    }
}

__global__ void __launch_bounds__(NTH, 1)
k_gi1(const float* __restrict__ Wih1, const float* __restrict__ bih1, int B)
{
    extern __shared__ char smc[];
    float* aux = (float*)(smc + SM_AUX);
    const int tid = threadIdx.x, w = tid >> 5, l = tid & 31;
    const int mw = w & 1, jw = w >> 1;
    const int bg0 = blockIdx.x * BT;
    const int nd = (16 * jw < 100) ? ((16 * jw + 8 < 100) ? 2 : 1) : 0;
    const uint32_t whi = sm32(smc + SM_WHI), wlo = sm32(smc + SM_WLO);

    setup_W(Wih1, smc, tid);
    for (int i = tid; i < 300; i += NTH) aux[i] = bih1[i];
    __syncthreads();
    stage_h(smc + SM_H, smc + SM_H + HBUF, 0, bg0, B, tid);
    __syncthreads();

    for (int t = 0; t < T; ++t) {
        char* hc = smc + SM_H + (t & 1) * 2 * HBUF;
        char* hn = smc + SM_H + ((t + 1) & 1) * 2 * HBUF;
        float acc[2][6][4];
        mma_all(whi, wlo, sm32(hc), sm32(hc + HBUF), jw, mw, l, nd, acc);

        if (t + 1 < T) stage_h(hn, hn + HBUF, t + 1, bg0, B, tid);

        float* gt = g_GI1 + (size_t)t * 3 * HID * B + bg0;
        #pragma unroll
        for (int i = 0; i < 2; ++i) {
            int mt = 2 * mw + i;
            int b0 = 16 * mt + (l >> 2), b1 = b0 + 8;
            #pragma unroll
            for (int d = 0; d < 2; ++d) {
                if (d < nd) {
                    int j0 = 16 * jw + 8 * d + 2 * (l & 3);
                    if (j0 < 100) {
                        float2 br = *(float2*)(aux + j0), bz = *(float2*)(aux + 100 + j0), bn = *(float2*)(aux + 200 + j0);
                        #pragma unroll
                        for (int g = 0; g < 3; ++g) {
                            float* a = acc[i][g * 2 + d];
                            float2 bs = (g == 0) ? br : ((g == 1) ? bz : bn);
                            float* p = gt + ((size_t)g * HID + j0) * B;
                            p[b0]     = a[0] + bs.x;
                            p[B + b0] = a[1] + bs.y;
                            p[b1]     = a[2] + bs.x;
                            p[B + b1] = a[3] + bs.y;
                        }
                    }
                }
            }
        }
        __syncthreads();
    }
}

// ---------------- K3: layer-1 recurrence + final linear ----------------
__device__ __forceinline__ void load_gi(float* gi, const float* gt, int B, int j0, int b0)
{
    int js = (j0 < 100) ? j0 : 0;
    int b1 = b0 + 8;
    #pragma unroll
    for (int g = 0; g < 3; ++g) {
        const float* p = gt + ((size_t)g * HID + js) * B;
        gi[g * 4 + 0] = p[b0];
        gi[g * 4 + 1] = p[B + b0];
        gi[g * 4 + 2] = p[b1];
        gi[g * 4 + 3] = p[B + b1];
    }
}

__global__ void __launch_bounds__(NTH, 1)
k_layer1(const float* __restrict__ Whh1, const float* __restrict__ bhh1,
         const float* __restrict__ Wlin, const float* __restrict__ blin,
         float* __restrict__ out, int iter, int B)
{
    extern __shared__ char smc[];
    float* aux = (float*)(smc + SM_AUX);   // [0:300) bhh, [304:404) wlin
    const int tid = threadIdx.x, w = tid >> 5, l = tid & 31;
    const int mw = w & 1, jw = w >> 1;
    const int bg0 = blockIdx.x * BT;
    const int nd = (16 * jw < 100) ? ((16 * jw + 8 < 100) ? 2 : 1) : 0;
    const uint32_t whi = sm32(smc + SM_WHI), wlo = sm32(smc + SM_WLO);

    setup_W(Whh1, smc, tid);
    for (int i = tid; i < 300; i += NTH) aux[i] = bhh1[i];
    for (int i = tid; i < HID; i += NTH)  aux[304 + i] = Wlin[i];
    __syncthreads();

    float hold[2][2][4];
    #pragma unroll
    for (int a = 0; a < 2; ++a)
        #pragma unroll
        for (int b = 0; b < 2; ++b)
            #pragma unroll
            for (int c = 0; c < 4; ++c) hold[a][b][c] = 0.f;

    const int step = (nd == 2) ? 1 : 2;
    for (int t = 0; t < T; ++t) {
        char* hc = smc + SM_H + (t & 1) * 2 * HBUF;
        char* hn = smc + SM_H + ((t + 1) & 1) * 2 * HBUF;
        const float* gt = g_GI1 + (size_t)t * 3 * HID * B + bg0;

        float gi[12] = {0};
        if (nd > 0) load_gi(gi, gt, B, 16 * jw + 2 * (l & 3), 16 * (2 * mw) + (l >> 2));

        float acc[2][6][4];
        mma_all(whi, wlo, sm32(hc), sm32(hc + HBUF), jw, mw, l, nd, acc);

        #pragma unroll
        for (int ci = 0; ci < 4; ++ci) {
            int i = ci >> 1, d = ci & 1;
            if (d < nd) {
                float gin[12] = {0};
                int nx = ci + step;
                if (nx < 4) {
                    int ni = nx >> 1, ndd = nx & 1;
                    load_gi(gin, gt, B, 16 * jw + 8 * ndd + 2 * (l & 3),
                            16 * (2 * mw + ni) + (l >> 2));
                }
                int mt = 2 * mw + i;
                int j0 = 16 * jw + 8 * d + 2 * (l & 3);
                int b0 = 16 * mt + (l >> 2), b1 = b0 + 8;
                bool jv = j0 < 100;
                int js = jv ? j0 : 0;
                float2 hr = *(float2*)(aux + js), hz = *(float2*)(aux + 100 + js), hn2 = *(float2*)(aux + 200 + js);
                float* ar = acc[i][0 + d]; float* az = acc[i][2 + d]; float* an = acc[i][4 + d];
                float h[4];
                #pragma unroll
                for (int c = 0; c < 4; ++c) {
                    float hrc = (c & 1) ? hr.y : hr.x, hzc = (c & 1) ? hz.y : hz.x, hnc = (c & 1) ? hn2.y : hn2.x;
                    float r = sigf(gi[0 + c] + ar[c] + hrc);
                    float z = sigf(gi[4 + c] + az[c] + hzc);
                    float n = tanhf_(gi[8 + c] + r * (an[c] + hnc));
                    h[c] = (1.f - z) * n + z * hold[i][d][c];
                    hold[i][d][c] = h[c];
                }
                if (jv) {
                    uint32_t hi0, lo0, hi1, lo1;
                    pack_hilo(h[0], h[1], hi0, lo0);
                    pack_hilo(h[2], h[3], hi1, lo1);
                    *(uint32_t*)(hn + b0 * LDB + j0 * 2)        = hi0;
                    *(uint32_t*)(hn + HBUF + b0 * LDB + j0 * 2) = lo0;
                    *(uint32_t*)(hn + b1 * LDB + j0 * 2)        = hi1;
                    *(uint32_t*)(hn + HBUF + b1 * LDB + j0 * 2) = lo1;
                }
                #pragma unroll
                for (int q = 0; q < 12; ++q) gi[q] = gin[q];
            }
        }
        __syncthreads();
    }

    // dump fp32 h to scratch (reuse W region), reduce with W_lin
    float* scr = (float*)(smc + SM_WHI);   // [j][b], 100*64 floats
    #pragma unroll
    for (int i = 0; i < 2; ++i) {
        int mt = 2 * mw + i;
        int b0 = 16 * mt + (l >> 2), b1 = b0 + 8;
        #pragma unroll
        for (int d = 0; d < 2; ++d) {
            if (d < nd) {
                int j0 = 16 * jw + 8 * d + 2 * (l & 3);
                if (j0 < 100) {
                    scr[j0 * 64 + b0]       = hold[i][d][0];
                    scr[(j0 + 1) * 64 + b0] = hold[i][d][1];
                    scr[j0 * 64 + b1]       = hold[i][d][2];
                    scr[(j0 + 1) * 64 + b1] = hold[i][d][3];
                }
            }
        }
    }
    __syncthreads();
    if (tid < BT) {
        float acc = blin[0];
        #pragma unroll 10
        for (int k = 0; k < HID; ++k) acc += scr[k * 64 + tid] * aux[304 + k];
        g_VBUF[(size_t)(T + iter) * B + bg0 + tid] = acc;
        out[(bg0 + tid) * NB + iter] = acc;
    }
}

extern "C" void kernel_launch(void* const* d_in, const int* in_sizes, int n_in,
                              void* d_out, int out_size)
{
    const float* x    = (const float*)d_in[0];
    const float* Wih0 = (const float*)d_in[1];
    const float* Whh0 = (const float*)d_in[2];
    const float* bih0 = (const float*)d_in[3];
    const float* bhh0 = (const float*)d_in[4];
    const float* Wih1 = (const float*)d_in[5];
    const float* Whh1 = (const float*)d_in[6];
    const float* bih1 = (const float*)d_in[7];
    const float* bhh1 = (const float*)d_in[8];
    const float* Wlin = (const float*)d_in[9];
    const float* blin = (const float*)d_in[10];
    float* out = (float*)d_out;

    const int B = in_sizes[0] / T;              // 65536

    cudaFuncSetAttribute(k_layer0, cudaFuncAttributeMaxDynamicSharedMemorySize, SMEM_BYTES);
    cudaFuncSetAttribute(k_gi1,    cudaFuncAttributeMaxDynamicSharedMemorySize, SMEM_BYTES);
    cudaFuncSetAttribute(k_layer1, cudaFuncAttributeMaxDynamicSharedMemorySize, SMEM_BYTES);

    k_init<<<(B * T + 511) / 512, 512>>>(x, B);

    const int nblk = B / BT;                    // 1024 CTAs
    for (int i = 0; i < NB; ++i) {
        k_layer0<<<nblk, NTH, SMEM_BYTES>>>(Whh0, Wih0, bih0, bhh0, i, B);
        k_gi1  <<<nblk, NTH, SMEM_BYTES>>>(Wih1, bih1, B);
        k_layer1<<<nblk, NTH, SMEM_BYTES>>>(Whh1, bhh1, Wlin, blin, out, i, B);
    }
}

// round 15
// speedup vs baseline: 2.5413x; 1.2432x over previous
#include <cuda_runtime.h>
#include <cuda_bf16.h>
#include <cstdint>

#define HID 100
#define T   10
#define NB  5
#define BT  64
#define NTH 512
#define B_MAX 65536
#define NC_MAX (B_MAX / BT)

#define LDB 240            // bf16 row stride in bytes (120 elems)
#define GATE_ROWS 104      // padded W rows per gate block
#define KTILES 7           // k = 112 (100 real + 12 zero)

// SMEM byte layout
#define SM_WHI 0
#define SM_WLO 74880       // 312 * 240
#define SM_H   149760      // 4 h buffers: [hi0, lo0, hi1, lo1], each 64*240
#define HBUF   15360
#define SM_AUX 211200      // 1024 floats aux
#define SMEM_BYTES 215296

// Scratch (static device memory; kernel_launch stays allocation-free)
__device__ float g_VBUF[(T + NB) * B_MAX];
// layer0 outputs, PRE-PACKED as the bf16 hi/lo ldsm tiles K2 consumes
__device__ __align__(16) char g_HB[(size_t)T * NC_MAX * 2 * HBUF];
// layer1 input gates, fragment-flat: [t][cta][slot 12][tid 512] x float4
__device__ float g_GI1[(size_t)T * NC_MAX * 12 * NTH * 4];

__device__ __forceinline__ float sigf(float x)   { return __fdividef(1.f, 1.f + __expf(-x)); }
__device__ __forceinline__ float tanhf_(float x) { return 1.f - __fdividef(2.f, __expf(2.f * x) + 1.f); }

__device__ __forceinline__ uint32_t sm32(const void* p) {
    return (uint32_t)__cvta_generic_to_shared(p);
}

__device__ __forceinline__ void cp16c(char* smem_dst, const char* gsrc) {
    unsigned sa = (unsigned)__cvta_generic_to_shared(smem_dst);
    asm volatile("cp.async.ca.shared.global [%0], [%1], 16;" :: "r"(sa), "l"(gsrc));
}
#define CP_COMMIT() asm volatile("cp.async.commit_group;" ::: "memory")
#define CP_WAIT0()  asm volatile("cp.async.wait_group 0;" ::: "memory")

__device__ __forceinline__ void ldsm_x4(uint32_t* r, uint32_t a) {
    asm volatile("ldmatrix.sync.aligned.m8n8.x4.shared.b16 {%0,%1,%2,%3}, [%4];"
        : "=r"(r[0]), "=r"(r[1]), "=r"(r[2]), "=r"(r[3]) : "r"(a));
}
__device__ __forceinline__ void ldsm_x2(uint32_t* r, uint32_t a) {
    asm volatile("ldmatrix.sync.aligned.m8n8.x2.shared.b16 {%0,%1}, [%2];"
        : "=r"(r[0]), "=r"(r[1]) : "r"(a));
}
__device__ __forceinline__ void mma_bf16(float* c, const uint32_t* a, const uint32_t* b) {
    asm volatile(
        "mma.sync.aligned.m16n8k16.row.col.f32.bf16.bf16.f32 "
        "{%0,%1,%2,%3}, {%4,%5,%6,%7}, {%8,%9}, {%0,%1,%2,%3};"
        : "+f"(c[0]), "+f"(c[1]), "+f"(c[2]), "+f"(c[3])
        : "r"(a[0]), "r"(a[1]), "r"(a[2]), "r"(a[3]), "r"(b[0]), "r"(b[1]));
}

__device__ __forceinline__ uint32_t pack_bf2(float a, float b) {
    __nv_bfloat162 v = __halves2bfloat162(__float2bfloat16(a), __float2bfloat16(b));
    return *reinterpret_cast<uint32_t*>(&v);
}
__device__ __forceinline__ void pack_hilo(float a, float b, uint32_t& hi, uint32_t& lo) {
    __nv_bfloat16 ha = __float2bfloat16(a), hb = __float2bfloat16(b);
    hi = pack_bf2(__bfloat162float(ha), __bfloat162float(hb));
    __nv_bfloat162 vh = *reinterpret_cast<__nv_bfloat162*>(&hi);
    lo = pack_bf2(a - __bfloat162float(vh.x), b - __bfloat162float(vh.y));
}

// 16 warps = (2 mw) x (8 jw). Warp computes M-tiles {2mw, 2mw+1} x its j-slots.
// acc[i 2][gate*2+d 6][c 4]; c: (b0,j0)(b0,j1)(b1,j0)(b1,j1), b0=16mt+l/4, b1=b0+8
__device__ __forceinline__ void mma_all(uint32_t whi, uint32_t wlo,
                                        uint32_t hhi, uint32_t hlo,
                                        int jw, int mw, int l, int nd,
                                        float acc[2][6][4])
{
    #pragma unroll
    for (int i = 0; i < 2; ++i)
        #pragma unroll
        for (int j = 0; j < 6; ++j)
            #pragma unroll
            for (int k = 0; k < 4; ++k) acc[i][j][k] = 0.f;
    if (nd == 0) return;

    const uint32_t a_hi = hhi + (l & 15) * LDB + ((l >> 4) << 4) + 2 * mw * 16 * LDB;
    const uint32_t a_lo = hlo + (l & 15) * LDB + ((l >> 4) << 4) + 2 * mw * 16 * LDB;
    const uint32_t brow = (l & 7) * LDB + (((l >> 3) & 1) << 4);

    #pragma unroll
    for (int kt = 0; kt < KTILES; ++kt) {
        uint32_t ah[2][4], al[2][4];
        #pragma unroll
        for (int i = 0; i < 2; ++i) {
            ldsm_x4(ah[i], a_hi + i * 16 * LDB + kt * 32);
            ldsm_x4(al[i], a_lo + i * 16 * LDB + kt * 32);
        }
        #pragma unroll
        for (int g = 0; g < 3; ++g) {
            #pragma unroll
            for (int d = 0; d < 2; ++d) {
                if (d < nd) {
                    uint32_t off = (g * GATE_ROWS + 16 * jw + 8 * d) * LDB + kt * 32 + brow;
                    uint32_t bh[2], bl[2];
                    ldsm_x2(bh, whi + off);
                    ldsm_x2(bl, wlo + off);
                    #pragma unroll
                    for (int i = 0; i < 2; ++i) {
                        mma_bf16(acc[i][g * 2 + d], ah[i], bh);
                        mma_bf16(acc[i][g * 2 + d], al[i], bh);
                        mma_bf16(acc[i][g * 2 + d], ah[i], bl);
                    }
                }
            }
        }
    }
}

// W [300][100] fp32 -> smem bf16 hi/lo tiles [gate*104 + j][k], zero-padded
__device__ void setup_W(const float* __restrict__ W, char* smc, int tid)
{
    float4 z4 = make_float4(0.f, 0.f, 0.f, 0.f);
    for (int i = tid; i < (SM_H - SM_WHI) / 16; i += NTH) ((float4*)(smc + SM_WHI))[i] = z4;
    for (int i = tid; i < 4 * HBUF / 16; i += NTH)        ((float4*)(smc + SM_H))[i]   = z4;
    __syncthreads();
    for (int idx = tid; idx < 3 * HID * HID; idx += NTH) {
        int g = idx / HID, k = idx - g * HID;
        int gate = g / HID, j = g - gate * HID;
        float v = W[idx];
        __nv_bfloat16 hi = __float2bfloat16(v);
        __nv_bfloat16 lo = __float2bfloat16(v - __bfloat162float(hi));
        uint32_t off = (uint32_t)(gate * GATE_ROWS + j) * LDB + k * 2;
        *(__nv_bfloat16*)(smc + SM_WHI + off) = hi;
        *(__nv_bfloat16*)(smc + SM_WLO + off) = lo;
    }
}

// ---------------- init: VBUF[s][b] = x[b][s] ----------------
__global__ void k_init(const float* __restrict__ x, int B)
{
    int idx = blockIdx.x * blockDim.x + threadIdx.x;
    if (idx < B * T) {
        int b = idx / T, s = idx - b * T;
        g_VBUF[s * B + b] = x[idx];
    }
}

// ---------------- K1: layer-0 recurrence ----------------
__global__ void __launch_bounds__(NTH, 1)
k_layer0(const float* __restrict__ Whh0, const float* __restrict__ Wih0,
         const float* __restrict__ bih0, const float* __restrict__ bhh0,
         int iter, int B)
{
    extern __shared__ char smc[];
    float* aux = (float*)(smc + SM_AUX);   // [0:300) wih, [304:604) bih, [608:908) bhh
    const int tid = threadIdx.x, w = tid >> 5, l = tid & 31;
    const int mw = w & 1, jw = w >> 1;
    const int bg0 = blockIdx.x * BT;
    const int nd = (16 * jw < 100) ? ((16 * jw + 8 < 100) ? 2 : 1) : 0;
    const uint32_t whi = sm32(smc + SM_WHI), wlo = sm32(smc + SM_WLO);

    setup_W(Whh0, smc, tid);
    for (int i = tid; i < 300; i += NTH) {
        aux[i] = Wih0[i]; aux[304 + i] = bih0[i]; aux[608 + i] = bhh0[i];
    }
    __syncthreads();

    float hold[2][2][4];
    #pragma unroll
    for (int a = 0; a < 2; ++a)
        #pragma unroll
        for (int b = 0; b < 2; ++b)
            #pragma unroll
            for (int c = 0; c < 4; ++c) hold[a][b][c] = 0.f;

    for (int t = 0; t < T; ++t) {
        char* hc = smc + SM_H + (t & 1) * 2 * HBUF;
        char* hn = smc + SM_H + ((t + 1) & 1) * 2 * HBUF;
        char* gb = g_HB + (size_t)(t * gridDim.x + blockIdx.x) * (2 * HBUF);
        float acc[2][6][4];
        mma_all(whi, wlo, sm32(hc), sm32(hc + HBUF), jw, mw, l, nd, acc);

        const float* xr = g_VBUF + (size_t)(iter + t) * B + bg0;
        #pragma unroll
        for (int i = 0; i < 2; ++i) {
            int mt = 2 * mw + i;
            int b0 = 16 * mt + (l >> 2), b1 = b0 + 8;
            float x0 = xr[b0], x1 = xr[b1];
            #pragma unroll
            for (int d = 0; d < 2; ++d) {
                int j0 = 16 * jw + 8 * d + 2 * (l & 3);
                if (d < nd && j0 < 100) {
                    float2 wr = *(float2*)(aux + j0),       wz = *(float2*)(aux + 100 + j0),       wn = *(float2*)(aux + 200 + j0);
                    float2 br = *(float2*)(aux + 304 + j0), bz = *(float2*)(aux + 404 + j0),       bn = *(float2*)(aux + 504 + j0);
                    float2 hr = *(float2*)(aux + 608 + j0), hz = *(float2*)(aux + 708 + j0),       hn2 = *(float2*)(aux + 808 + j0);
                    float* ar = acc[i][0 + d]; float* az = acc[i][2 + d]; float* an = acc[i][4 + d];
                    float h[4];
                    #pragma unroll
                    for (int c = 0; c < 4; ++c) {
                        float xv = (c < 2) ? x0 : x1;
                        float wrc = (c & 1) ? wr.y : wr.x, wzc = (c & 1) ? wz.y : wz.x, wnc = (c & 1) ? wn.y : wn.x;
                        float brc = (c & 1) ? br.y : br.x, bzc = (c & 1) ? bz.y : bz.x, bnc = (c & 1) ? bn.y : bn.x;
                        float hrc = (c & 1) ? hr.y : hr.x, hzc = (c & 1) ? hz.y : hz.x, hnc = (c & 1) ? hn2.y : hn2.x;
                        float r = sigf(xv * wrc + brc + ar[c] + hrc);
                        float z = sigf(xv * wzc + bzc + az[c] + hzc);
                        float n = tanhf_(xv * wnc + bnc + r * (an[c] + hnc));
                        h[c] = (1.f - z) * n + z * hold[i][d][c];
                        hold[i][d][c] = h[c];
                    }
                    uint32_t hi0, lo0, hi1, lo1;
                    pack_hilo(h[0], h[1], hi0, lo0);
                    pack_hilo(h[2], h[3], hi1, lo1);
                    *(uint32_t*)(hn + b0 * LDB + j0 * 2)        = hi0;
                    *(uint32_t*)(hn + HBUF + b0 * LDB + j0 * 2) = lo0;
                    *(uint32_t*)(hn + b1 * LDB + j0 * 2)        = hi1;
                    *(uint32_t*)(hn + HBUF + b1 * LDB + j0 * 2) = lo1;
                    // pre-packed tile for K2 (same words)
                    *(uint32_t*)(gb + b0 * LDB + j0 * 2)        = hi0;
                    *(uint32_t*)(gb + HBUF + b0 * LDB + j0 * 2) = lo0;
                    *(uint32_t*)(gb + b1 * LDB + j0 * 2)        = hi1;
                    *(uint32_t*)(gb + HBUF + b1 * LDB + j0 * 2) = lo1;
                } else if (j0 < 112) {
                    // zero-fill padded k region so K2's tiles stay exact
                    *(uint32_t*)(gb + b0 * LDB + j0 * 2)        = 0u;
                    *(uint32_t*)(gb + HBUF + b0 * LDB + j0 * 2) = 0u;
                    *(uint32_t*)(gb + b1 * LDB + j0 * 2)        = 0u;
                    *(uint32_t*)(gb + HBUF + b1 * LDB + j0 * 2) = 0u;
                }
            }
        }
        __syncthreads();
    }
}

// ---------------- K2: GI1[t] = Wih1 * H1[t] + b_ih1 ----------------
__device__ __forceinline__ void stage_hb(char* dst, const char* src, int tid)
{
    for (int i = tid; i < 2 * HBUF / 16; i += NTH)
        cp16c(dst + i * 16, src + i * 16);
}

__global__ void __launch_bounds__(NTH, 1)
k_gi1(const float* __restrict__ Wih1, const float* __restrict__ bih1, int B)
{
    extern __shared__ char smc[];
    float* aux = (float*)(smc + SM_AUX);
    const int tid = threadIdx.x, w = tid >> 5, l = tid & 31;
    const int mw = w & 1, jw = w >> 1;
    const int nd = (16 * jw < 100) ? ((16 * jw + 8 < 100) ? 2 : 1) : 0;
    const uint32_t whi = sm32(smc + SM_WHI), wlo = sm32(smc + SM_WLO);

    setup_W(Wih1, smc, tid);
    for (int i = tid; i < 300; i += NTH) aux[i] = bih1[i];

    stage_hb(smc + SM_H, g_HB + (size_t)blockIdx.x * (2 * HBUF), tid);
    CP_COMMIT();
    CP_WAIT0();
    __syncthreads();

    for (int t = 0; t < T; ++t) {
        char* hc = smc + SM_H + (t & 1) * 2 * HBUF;
        char* hn = smc + SM_H + ((t + 1) & 1) * 2 * HBUF;
        if (t + 1 < T) {
            stage_hb(hn, g_HB + (size_t)((t + 1) * gridDim.x + blockIdx.x) * (2 * HBUF), tid);
            CP_COMMIT();
        }

        float acc[2][6][4];
        mma_all(whi, wlo, sm32(hc), sm32(hc + HBUF), jw, mw, l, nd, acc);

        if (nd > 0) {
            float* bt = g_GI1 + ((size_t)(t * gridDim.x + blockIdx.x) * 12 * NTH + tid) * 4;
            int j0b = 16 * jw + 2 * (l & 3);
            #pragma unroll
            for (int i = 0; i < 2; ++i) {
                #pragma unroll
                for (int d = 0; d < 2; ++d) {
                    int j0 = j0b + 8 * d;
                    int js = (j0 < 100) ? j0 : 0;
                    float2 br = *(float2*)(aux + js), bz = *(float2*)(aux + 100 + js), bn = *(float2*)(aux + 200 + js);
                    #pragma unroll
                    for (int g = 0; g < 3; ++g) {
                        float* a = acc[i][g * 2 + d];
                        float2 bs = (g == 0) ? br : ((g == 1) ? bz : bn);
                        int slot = (i * 2 + d) * 3 + g;
                        *(float4*)(bt + (size_t)slot * NTH * 4) =
                            make_float4(a[0] + bs.x, a[1] + bs.y, a[2] + bs.x, a[3] + bs.y);
                    }
                }
            }
        }
        CP_WAIT0();
        __syncthreads();
    }
}

// ---------------- K3: layer-1 recurrence + final linear ----------------
__device__ __forceinline__ void load_gi_flat(float* gi, const float* bt, int slot0)
{
    #pragma unroll
    for (int g = 0; g < 3; ++g)
        *(float4*)(gi + g * 4) = *(const float4*)(bt + (size_t)(slot0 + g) * NTH * 4);
}

__global__ void __launch_bounds__(NTH, 1)
k_layer1(const float* __restrict__ Whh1, const float* __restrict__ bhh1,
         const float* __restrict__ Wlin, const float* __restrict__ blin,
         float* __restrict__ out, int iter, int B)
{
    extern __shared__ char smc[];
    float* aux = (float*)(smc + SM_AUX);   // [0:300) bhh, [304:404) wlin
    const int tid = threadIdx.x, w = tid >> 5, l = tid & 31;
    const int mw = w & 1, jw = w >> 1;
    const int bg0 = blockIdx.x * BT;
    const int nd = (16 * jw < 100) ? ((16 * jw + 8 < 100) ? 2 : 1) : 0;
    const uint32_t whi = sm32(smc + SM_WHI), wlo = sm32(smc + SM_WLO);

    setup_W(Whh1, smc, tid);
    for (int i = tid; i < 300; i += NTH) aux[i] = bhh1[i];
    for (int i = tid; i < HID; i += NTH)  aux[304 + i] = Wlin[i];
    __syncthreads();

    float hold[2][2][4];
    #pragma unroll
    for (int a = 0; a < 2; ++a)
        #pragma unroll
        for (int b = 0; b < 2; ++b)
            #pragma unroll
            for (int c = 0; c < 4; ++c) hold[a][b][c] = 0.f;

    const int step = (nd == 2) ? 1 : 2;
    for (int t = 0; t < T; ++t) {
        char* hc = smc + SM_H + (t & 1) * 2 * HBUF;
        char* hn = smc + SM_H + ((t + 1) & 1) * 2 * HBUF;
        const float* bt = g_GI1 + ((size_t)(t * gridDim.x + blockIdx.x) * 12 * NTH + tid) * 4;

        float gi[12] = {0};
        if (nd > 0) load_gi_flat(gi, bt, 0);

        float acc[2][6][4];
        mma_all(whi, wlo, sm32(hc), sm32(hc + HBUF), jw, mw, l, nd, acc);

        #pragma unroll
        for (int ci = 0; ci < 4; ++ci) {
            int i = ci >> 1, d = ci & 1;
            if (d < nd) {
                float gin[12] = {0};
                int nx = ci + step;
                if (nx < 4) load_gi_flat(gin, bt, nx * 3);

                int mt = 2 * mw + i;
                int j0 = 16 * jw + 8 * d + 2 * (l & 3);
                int b0 = 16 * mt + (l >> 2), b1 = b0 + 8;
                bool jv = j0 < 100;
                int js = jv ? j0 : 0;
                float2 hr = *(float2*)(aux + js), hz = *(float2*)(aux + 100 + js), hn2 = *(float2*)(aux + 200 + js);
                float* ar = acc[i][0 + d]; float* az = acc[i][2 + d]; float* an = acc[i][4 + d];
                float h[4];
                #pragma unroll
                for (int c = 0; c < 4; ++c) {
                    float hrc = (c & 1) ? hr.y : hr.x, hzc = (c & 1) ? hz.y : hz.x, hnc = (c & 1) ? hn2.y : hn2.x;
                    float r = sigf(gi[0 + c] + ar[c] + hrc);
                    float z = sigf(gi[4 + c] + az[c] + hzc);
                    float n = tanhf_(gi[8 + c] + r * (an[c] + hnc));
                    h[c] = (1.f - z) * n + z * hold[i][d][c];
                    hold[i][d][c] = h[c];
                }
                if (jv) {
                    uint32_t hi0, lo0, hi1, lo1;
                    pack_hilo(h[0], h[1], hi0, lo0);
                    pack_hilo(h[2], h[3], hi1, lo1);
                    *(uint32_t*)(hn + b0 * LDB + j0 * 2)        = hi0;
                    *(uint32_t*)(hn + HBUF + b0 * LDB + j0 * 2) = lo0;
                    *(uint32_t*)(hn + b1 * LDB + j0 * 2)        = hi1;
                    *(uint32_t*)(hn + HBUF + b1 * LDB + j0 * 2) = lo1;
                }
                #pragma unroll
                for (int q = 0; q < 12; ++q) gi[q] = gin[q];
            }
        }
        __syncthreads();
    }

    // dump fp32 h to scratch (reuse W region), reduce with W_lin
    float* scr = (float*)(smc + SM_WHI);   // [j][b], 100*64 floats
    #pragma unroll
    for (int i = 0; i < 2; ++i) {
        int mt = 2 * mw + i;
        int b0 = 16 * mt + (l >> 2), b1 = b0 + 8;
        #pragma unroll
        for (int d = 0; d < 2; ++d) {
            if (d < nd) {
                int j0 = 16 * jw + 8 * d + 2 * (l & 3);
                if (j0 < 100) {
                    scr[j0 * 64 + b0]       = hold[i][d][0];
                    scr[(j0 + 1) * 64 + b0] = hold[i][d][1];
                    scr[j0 * 64 + b1]       = hold[i][d][2];
                    scr[(j0 + 1) * 64 + b1] = hold[i][d][3];
                }
            }
        }
    }
    __syncthreads();
    if (tid < BT) {
        float acc = blin[0];
        #pragma unroll 10
        for (int k = 0; k < HID; ++k) acc += scr[k * 64 + tid] * aux[304 + k];
        g_VBUF[(size_t)(T + iter) * B + bg0 + tid] = acc;
        out[(bg0 + tid) * NB + iter] = acc;
    }
}

extern "C" void kernel_launch(void* const* d_in, const int* in_sizes, int n_in,
                              void* d_out, int out_size)
{
    const float* x    = (const float*)d_in[0];
    const float* Wih0 = (const float*)d_in[1];
    const float* Whh0 = (const float*)d_in[2];
    const float* bih0 = (const float*)d_in[3];
    const float* bhh0 = (const float*)d_in[4];
    const float* Wih1 = (const float*)d_in[5];
    const float* Whh1 = (const float*)d_in[6];
    const float* bih1 = (const float*)d_in[7];
    const float* bhh1 = (const float*)d_in[8];
    const float* Wlin = (const float*)d_in[9];
    const float* blin = (const float*)d_in[10];
    float* out = (float*)d_out;

    const int B = in_sizes[0] / T;              // 65536

    cudaFuncSetAttribute(k_layer0, cudaFuncAttributeMaxDynamicSharedMemorySize, SMEM_BYTES);
    cudaFuncSetAttribute(k_gi1,    cudaFuncAttributeMaxDynamicSharedMemorySize, SMEM_BYTES);
    cudaFuncSetAttribute(k_layer1, cudaFuncAttributeMaxDynamicSharedMemorySize, SMEM_BYTES);

    k_init<<<(B * T + 511) / 512, 512>>>(x, B);

    const int nblk = B / BT;                    // 1024 CTAs
    for (int i = 0; i < NB; ++i) {
        k_layer0<<<nblk, NTH, SMEM_BYTES>>>(Whh0, Wih0, bih0, bhh0, i, B);
        k_gi1  <<<nblk, NTH, SMEM_BYTES>>>(Wih1, bih1, B);
        k_layer1<<<nblk, NTH, SMEM_BYTES>>>(Whh1, bhh1, Wlin, blin, out, i, B);
    }
}

// round 16
// speedup vs baseline: 2.6811x; 1.0550x over previous
#include <cuda_runtime.h>
#include <cuda_bf16.h>
#include <cstdint>

#define HID 100
#define T   10
#define NB  5
#define BT  64
#define NTH 1024
#define B_MAX 65536
#define NC_MAX (B_MAX / BT)

#define LDB 240            // bf16 row stride in bytes (120 elems)
#define GATE_ROWS 104      // padded W rows per gate block
#define KTILES 7           // k = 112 (100 real + 12 zero)

// SMEM byte layout
#define SM_WHI 0
#define SM_WLO 74880       // 312 * 240
#define SM_H   149760      // 4 h buffers: [hi0, lo0, hi1, lo1], each 64*240
#define HBUF   15360
#define SM_AUX 211200      // 1024 floats aux
#define SMEM_BYTES 215296

// Scratch (static device memory; kernel_launch stays allocation-free)
__device__ float g_VBUF[(T + NB) * B_MAX];
// layer0 outputs, PRE-PACKED as the bf16 hi/lo ldsm tiles K2 consumes
__device__ __align__(16) char g_HB[(size_t)T * NC_MAX * 2 * HBUF];
// layer1 input gates, fragment-flat: [t][cta][slot 6][tid 1024] x float4
__device__ float g_GI1[(size_t)T * NC_MAX * 6 * NTH * 4];

__device__ __forceinline__ float sigf(float x)   { return __fdividef(1.f, 1.f + __expf(-x)); }
__device__ __forceinline__ float tanhf_(float x) { return 1.f - __fdividef(2.f, __expf(2.f * x) + 1.f); }

__device__ __forceinline__ uint32_t sm32(const void* p) {
    return (uint32_t)__cvta_generic_to_shared(p);
}

__device__ __forceinline__ void cp16c(char* smem_dst, const char* gsrc) {
    unsigned sa = (unsigned)__cvta_generic_to_shared(smem_dst);
    asm volatile("cp.async.ca.shared.global [%0], [%1], 16;" :: "r"(sa), "l"(gsrc));
}
#define CP_COMMIT() asm volatile("cp.async.commit_group;" ::: "memory")
#define CP_WAIT0()  asm volatile("cp.async.wait_group 0;" ::: "memory")

__device__ __forceinline__ void ldsm_x4(uint32_t* r, uint32_t a) {
    asm volatile("ldmatrix.sync.aligned.m8n8.x4.shared.b16 {%0,%1,%2,%3}, [%4];"
        : "=r"(r[0]), "=r"(r[1]), "=r"(r[2]), "=r"(r[3]) : "r"(a));
}
__device__ __forceinline__ void ldsm_x2(uint32_t* r, uint32_t a) {
    asm volatile("ldmatrix.sync.aligned.m8n8.x2.shared.b16 {%0,%1}, [%2];"
        : "=r"(r[0]), "=r"(r[1]) : "r"(a));
}
__device__ __forceinline__ void mma_bf16(float* c, const uint32_t* a, const uint32_t* b) {
    asm volatile(
        "mma.sync.aligned.m16n8k16.row.col.f32.bf16.bf16.f32 "
        "{%0,%1,%2,%3}, {%4,%5,%6,%7}, {%8,%9}, {%0,%1,%2,%3};"
        : "+f"(c[0]), "+f"(c[1]), "+f"(c[2]), "+f"(c[3])
        : "r"(a[0]), "r"(a[1]), "r"(a[2]), "r"(a[3]), "r"(b[0]), "r"(b[1]));
}

__device__ __forceinline__ uint32_t pack_bf2(float a, float b) {
    __nv_bfloat162 v = __halves2bfloat162(__float2bfloat16(a), __float2bfloat16(b));
    return *reinterpret_cast<uint32_t*>(&v);
}
__device__ __forceinline__ void pack_hilo(float a, float b, uint32_t& hi, uint32_t& lo) {
    __nv_bfloat16 ha = __float2bfloat16(a), hb = __float2bfloat16(b);
    hi = pack_bf2(__bfloat162float(ha), __bfloat162float(hb));
    __nv_bfloat162 vh = *reinterpret_cast<__nv_bfloat162*>(&hi);
    lo = pack_bf2(a - __bfloat162float(vh.x), b - __bfloat162float(vh.y));
}

// 32 warps = (4 mw) x (8 jw). Warp computes M-tile mt = mw (16 batches) x its
// j-slots: j0 = 16jw + 8d + 2(l&3), d < nd.
// acc[gate*2+d 6][c 4]; c: (b0,j0)(b0,j1)(b1,j0)(b1,j1), b0=16mw+l/4, b1=b0+8
__device__ __forceinline__ void mma_all(uint32_t whi, uint32_t wlo,
                                        uint32_t hhi, uint32_t hlo,
                                        int jw, int mw, int l, int nd,
                                        float acc[6][4])
{
    #pragma unroll
    for (int j = 0; j < 6; ++j)
        #pragma unroll
        for (int k = 0; k < 4; ++k) acc[j][k] = 0.f;
    if (nd == 0) return;

    const uint32_t a_hi = hhi + (l & 15) * LDB + ((l >> 4) << 4) + mw * 16 * LDB;
    const uint32_t a_lo = hlo + (l & 15) * LDB + ((l >> 4) << 4) + mw * 16 * LDB;
    const uint32_t brow = (l & 7) * LDB + (((l >> 3) & 1) << 4);

    #pragma unroll
    for (int kt = 0; kt < KTILES; ++kt) {
        uint32_t ah[4], al[4];
        ldsm_x4(ah, a_hi + kt * 32);
        ldsm_x4(al, a_lo + kt * 32);
        #pragma unroll
        for (int g = 0; g < 3; ++g) {
            #pragma unroll
            for (int d = 0; d < 2; ++d) {
                if (d < nd) {
                    uint32_t off = (g * GATE_ROWS + 16 * jw + 8 * d) * LDB + kt * 32 + brow;
                    uint32_t bh[2], bl[2];
                    ldsm_x2(bh, whi + off);
                    ldsm_x2(bl, wlo + off);
                    mma_bf16(acc[g * 2 + d], ah, bh);
                    mma_bf16(acc[g * 2 + d], al, bh);
                    mma_bf16(acc[g * 2 + d], ah, bl);
                }
            }
        }
    }
}

// W [300][100] fp32 -> smem bf16 hi/lo tiles [gate*104 + j][k], zero-padded
__device__ void setup_W(const float* __restrict__ W, char* smc, int tid)
{
    float4 z4 = make_float4(0.f, 0.f, 0.f, 0.f);
    for (int i = tid; i < (SM_H - SM_WHI) / 16; i += NTH) ((float4*)(smc + SM_WHI))[i] = z4;
    for (int i = tid; i < 4 * HBUF / 16; i += NTH)        ((float4*)(smc + SM_H))[i]   = z4;
    __syncthreads();
    for (int idx = tid; idx < 3 * HID * HID; idx += NTH) {
        int g = idx / HID, k = idx - g * HID;
        int gate = g / HID, j = g - gate * HID;
        float v = W[idx];
        __nv_bfloat16 hi = __float2bfloat16(v);
        __nv_bfloat16 lo = __float2bfloat16(v - __bfloat162float(hi));
        uint32_t off = (uint32_t)(gate * GATE_ROWS + j) * LDB + k * 2;
        *(__nv_bfloat16*)(smc + SM_WHI + off) = hi;
        *(__nv_bfloat16*)(smc + SM_WLO + off) = lo;
    }
}

// ---------------- init: VBUF[s][b] = x[b][s] ----------------
__global__ void k_init(const float* __restrict__ x, int B)
{
    int idx = blockIdx.x * blockDim.x + threadIdx.x;
    if (idx < B * T) {
        int b = idx / T, s = idx - b * T;
        g_VBUF[s * B + b] = x[idx];
    }
}

// ---------------- K1: layer-0 recurrence ----------------
__global__ void __launch_bounds__(NTH, 1)
k_layer0(const float* __restrict__ Whh0, const float* __restrict__ Wih0,
         const float* __restrict__ bih0, const float* __restrict__ bhh0,
         int iter, int B)
{
    extern __shared__ char smc[];
    float* aux = (float*)(smc + SM_AUX);   // [0:300) wih, [304:604) bih, [608:908) bhh
    const int tid = threadIdx.x, w = tid >> 5, l = tid & 31;
    const int mw = w & 3, jw = w >> 2;
    const int bg0 = blockIdx.x * BT;
    const int nd = (16 * jw < 100) ? ((16 * jw + 8 < 100) ? 2 : 1) : 0;
    const uint32_t whi = sm32(smc + SM_WHI), wlo = sm32(smc + SM_WLO);

    setup_W(Whh0, smc, tid);
    for (int i = tid; i < 300; i += NTH) {
        aux[i] = Wih0[i]; aux[304 + i] = bih0[i]; aux[608 + i] = bhh0[i];
    }
    __syncthreads();

    float hold[2][4];
    #pragma unroll
    for (int b = 0; b < 2; ++b)
        #pragma unroll
        for (int c = 0; c < 4; ++c) hold[b][c] = 0.f;

    for (int t = 0; t < T; ++t) {
        char* hc = smc + SM_H + (t & 1) * 2 * HBUF;
        char* hn = smc + SM_H + ((t + 1) & 1) * 2 * HBUF;
        char* gb = g_HB + (size_t)(t * gridDim.x + blockIdx.x) * (2 * HBUF);
        float acc[6][4];
        mma_all(whi, wlo, sm32(hc), sm32(hc + HBUF), jw, mw, l, nd, acc);

        const float* xr = g_VBUF + (size_t)(iter + t) * B + bg0;
        const int b0 = 16 * mw + (l >> 2), b1 = b0 + 8;
        const float x0 = xr[b0], x1 = xr[b1];
        #pragma unroll
        for (int d = 0; d < 2; ++d) {
            int j0 = 16 * jw + 8 * d + 2 * (l & 3);
            if (d < nd && j0 < 100) {
                float2 wr = *(float2*)(aux + j0),       wz = *(float2*)(aux + 100 + j0),       wn = *(float2*)(aux + 200 + j0);
                float2 br = *(float2*)(aux + 304 + j0), bz = *(float2*)(aux + 404 + j0),       bn = *(float2*)(aux + 504 + j0);
                float2 hr = *(float2*)(aux + 608 + j0), hz = *(float2*)(aux + 708 + j0),       hn2 = *(float2*)(aux + 808 + j0);
                float* ar = acc[0 + d]; float* az = acc[2 + d]; float* an = acc[4 + d];
                float h[4];
                #pragma unroll
                for (int c = 0; c < 4; ++c) {
                    float xv = (c < 2) ? x0 : x1;
                    float wrc = (c & 1) ? wr.y : wr.x, wzc = (c & 1) ? wz.y : wz.x, wnc = (c & 1) ? wn.y : wn.x;
                    float brc = (c & 1) ? br.y : br.x, bzc = (c & 1) ? bz.y : bz.x, bnc = (c & 1) ? bn.y : bn.x;
                    float hrc = (c & 1) ? hr.y : hr.x, hzc = (c & 1) ? hz.y : hz.x, hnc = (c & 1) ? hn2.y : hn2.x;
                    float r = sigf(xv * wrc + brc + ar[c] + hrc);
                    float z = sigf(xv * wzc + bzc + az[c] + hzc);
                    float n = tanhf_(xv * wnc + bnc + r * (an[c] + hnc));
                    h[c] = (1.f - z) * n + z * hold[d][c];
                    hold[d][c] = h[c];
                }
                uint32_t hi0, lo0, hi1, lo1;
                pack_hilo(h[0], h[1], hi0, lo0);
                pack_hilo(h[2], h[3], hi1, lo1);
                *(uint32_t*)(hn + b0 * LDB + j0 * 2)        = hi0;
                *(uint32_t*)(hn + HBUF + b0 * LDB + j0 * 2) = lo0;
                *(uint32_t*)(hn + b1 * LDB + j0 * 2)        = hi1;
                *(uint32_t*)(hn + HBUF + b1 * LDB + j0 * 2) = lo1;
                // pre-packed tile for K2 (same words)
                *(uint32_t*)(gb + b0 * LDB + j0 * 2)        = hi0;
                *(uint32_t*)(gb + HBUF + b0 * LDB + j0 * 2) = lo0;
                *(uint32_t*)(gb + b1 * LDB + j0 * 2)        = hi1;
                *(uint32_t*)(gb + HBUF + b1 * LDB + j0 * 2) = lo1;
            } else if (j0 < 112) {
                // zero-fill padded k region so K2's tiles stay exact
                *(uint32_t*)(gb + b0 * LDB + j0 * 2)        = 0u;
                *(uint32_t*)(gb + HBUF + b0 * LDB + j0 * 2) = 0u;
                *(uint32_t*)(gb + b1 * LDB + j0 * 2)        = 0u;
                *(uint32_t*)(gb + HBUF + b1 * LDB + j0 * 2) = 0u;
            }
        }
        __syncthreads();
    }
}

// ---------------- K2: GI1[t] = Wih1 * H1[t] + b_ih1 ----------------
__device__ __forceinline__ void stage_hb(char* dst, const char* src, int tid)
{
    for (int i = tid; i < 2 * HBUF / 16; i += NTH)
        cp16c(dst + i * 16, src + i * 16);
}

__global__ void __launch_bounds__(NTH, 1)
k_gi1(const float* __restrict__ Wih1, const float* __restrict__ bih1, int B)
{
    extern __shared__ char smc[];
    float* aux = (float*)(smc + SM_AUX);
    const int tid = threadIdx.x, w = tid >> 5, l = tid & 31;
    const int mw = w & 3, jw = w >> 2;
    const int nd = (16 * jw < 100) ? ((16 * jw + 8 < 100) ? 2 : 1) : 0;
    const uint32_t whi = sm32(smc + SM_WHI), wlo = sm32(smc + SM_WLO);

    setup_W(Wih1, smc, tid);
    for (int i = tid; i < 300; i += NTH) aux[i] = bih1[i];

    stage_hb(smc + SM_H, g_HB + (size_t)blockIdx.x * (2 * HBUF), tid);
    CP_COMMIT();
    CP_WAIT0();
    __syncthreads();

    for (int t = 0; t < T; ++t) {
        char* hc = smc + SM_H + (t & 1) * 2 * HBUF;
        char* hn = smc + SM_H + ((t + 1) & 1) * 2 * HBUF;
        if (t + 1 < T) {
            stage_hb(hn, g_HB + (size_t)((t + 1) * gridDim.x + blockIdx.x) * (2 * HBUF), tid);
            CP_COMMIT();
        }

        float acc[6][4];
        mma_all(whi, wlo, sm32(hc), sm32(hc + HBUF), jw, mw, l, nd, acc);

        if (nd > 0) {
            float* bt = g_GI1 + ((size_t)(t * gridDim.x + blockIdx.x) * 6 * NTH + tid) * 4;
            int j0b = 16 * jw + 2 * (l & 3);
            #pragma unroll
            for (int d = 0; d < 2; ++d) {
                int j0 = j0b + 8 * d;
                int js = (j0 < 100) ? j0 : 0;
                float2 br = *(float2*)(aux + js), bz = *(float2*)(aux + 100 + js), bn = *(float2*)(aux + 200 + js);
                #pragma unroll
                for (int g = 0; g < 3; ++g) {
                    float* a = acc[g * 2 + d];
                    float2 bs = (g == 0) ? br : ((g == 1) ? bz : bn);
                    int slot = d * 3 + g;
                    *(float4*)(bt + (size_t)slot * NTH * 4) =
                        make_float4(a[0] + bs.x, a[1] + bs.y, a[2] + bs.x, a[3] + bs.y);
                }
            }
        }
        CP_WAIT0();
        __syncthreads();
    }
}

// ---------------- K3: layer-1 recurrence + final linear ----------------
__global__ void __launch_bounds__(NTH, 1)
k_layer1(const float* __restrict__ Whh1, const float* __restrict__ bhh1,
         const float* __restrict__ Wlin, const float* __restrict__ blin,
         float* __restrict__ out, int iter, int B)
{
    extern __shared__ char smc[];
    float* aux = (float*)(smc + SM_AUX);   // [0:300) bhh, [304:404) wlin
    const int tid = threadIdx.x, w = tid >> 5, l = tid & 31;
    const int mw = w & 3, jw = w >> 2;
    const int bg0 = blockIdx.x * BT;
    const int nd = (16 * jw < 100) ? ((16 * jw + 8 < 100) ? 2 : 1) : 0;
    const uint32_t whi = sm32(smc + SM_WHI), wlo = sm32(smc + SM_WLO);

    setup_W(Whh1, smc, tid);
    for (int i = tid; i < 300; i += NTH) aux[i] = bhh1[i];
    for (int i = tid; i < HID; i += NTH)  aux[304 + i] = Wlin[i];
    __syncthreads();

    float hold[2][4];
    #pragma unroll
    for (int b = 0; b < 2; ++b)
        #pragma unroll
        for (int c = 0; c < 4; ++c) hold[b][c] = 0.f;

    for (int t = 0; t < T; ++t) {
        char* hc = smc + SM_H + (t & 1) * 2 * HBUF;
        char* hn = smc + SM_H + ((t + 1) & 1) * 2 * HBUF;
        const float* bt = g_GI1 + ((size_t)(t * gridDim.x + blockIdx.x) * 6 * NTH + tid) * 4;

        float acc[6][4];
        mma_all(whi, wlo, sm32(hc), sm32(hc + HBUF), jw, mw, l, nd, acc);

        const int b0 = 16 * mw + (l >> 2), b1 = b0 + 8;
        #pragma unroll
        for (int d = 0; d < 2; ++d) {
            if (d < nd) {
                float gi[12];
                #pragma unroll
                for (int g = 0; g < 3; ++g)
                    *(float4*)(gi + g * 4) = *(const float4*)(bt + (size_t)(d * 3 + g) * NTH * 4);

                int j0 = 16 * jw + 8 * d + 2 * (l & 3);
                bool jv = j0 < 100;
                int js = jv ? j0 : 0;
                float2 hr = *(float2*)(aux + js), hz = *(float2*)(aux + 100 + js), hn2 = *(float2*)(aux + 200 + js);
                float* ar = acc[0 + d]; float* az = acc[2 + d]; float* an = acc[4 + d];
                float h[4];
                #pragma unroll
                for (int c = 0; c < 4; ++c) {
                    float hrc = (c & 1) ? hr.y : hr.x, hzc = (c & 1) ? hz.y : hz.x, hnc = (c & 1) ? hn2.y : hn2.x;
                    float r = sigf(gi[0 + c] + ar[c] + hrc);
                    float z = sigf(gi[4 + c] + az[c] + hzc);
                    float n = tanhf_(gi[8 + c] + r * (an[c] + hnc));
                    h[c] = (1.f - z) * n + z * hold[d][c];
                    hold[d][c] = h[c];
                }
                if (jv) {
                    uint32_t hi0, lo0, hi1, lo1;
                    pack_hilo(h[0], h[1], hi0, lo0);
                    pack_hilo(h[2], h[3], hi1, lo1);
                    *(uint32_t*)(hn + b0 * LDB + j0 * 2)        = hi0;
                    *(uint32_t*)(hn + HBUF + b0 * LDB + j0 * 2) = lo0;
                    *(uint32_t*)(hn + b1 * LDB + j0 * 2)        = hi1;
                    *(uint32_t*)(hn + HBUF + b1 * LDB + j0 * 2) = lo1;
                }
            }
        }
        __syncthreads();
    }

    // dump fp32 h to scratch (reuse W region), reduce with W_lin
    float* scr = (float*)(smc + SM_WHI);   // [j][b], 100*64 floats
    {
        const int b0 = 16 * mw + (l >> 2), b1 = b0 + 8;
        #pragma unroll
        for (int d = 0; d < 2; ++d) {
            if (d < nd) {
                int j0 = 16 * jw + 8 * d + 2 * (l & 3);
                if (j0 < 100) {
                    scr[j0 * 64 + b0]       = hold[d][0];
                    scr[(j0 + 1) * 64 + b0] = hold[d][1];
                    scr[j0 * 64 + b1]       = hold[d][2];
                    scr[(j0 + 1) * 64 + b1] = hold[d][3];
                }
            }
        }
    }
    __syncthreads();
    if (tid < BT) {
        float acc = blin[0];
        #pragma unroll 10
        for (int k = 0; k < HID; ++k) acc += scr[k * 64 + tid] * aux[304 + k];
        g_VBUF[(size_t)(T + iter) * B + bg0 + tid] = acc;
        out[(bg0 + tid) * NB + iter] = acc;
    }
}

extern "C" void kernel_launch(void* const* d_in, const int* in_sizes, int n_in,
                              void* d_out, int out_size)
{
    const float* x    = (const float*)d_in[0];
    const float* Wih0 = (const float*)d_in[1];
    const float* Whh0 = (const float*)d_in[2];
    const float* bih0 = (const float*)d_in[3];
    const float* bhh0 = (const float*)d_in[4];
    const float* Wih1 = (const float*)d_in[5];
    const float* Whh1 = (const float*)d_in[6];
    const float* bih1 = (const float*)d_in[7];
    const float* bhh1 = (const float*)d_in[8];
    const float* Wlin = (const float*)d_in[9];
    const float* blin = (const float*)d_in[10];
    float* out = (float*)d_out;

    const int B = in_sizes[0] / T;              // 65536

    cudaFuncSetAttribute(k_layer0, cudaFuncAttributeMaxDynamicSharedMemorySize, SMEM_BYTES);
    cudaFuncSetAttribute(k_gi1,    cudaFuncAttributeMaxDynamicSharedMemorySize, SMEM_BYTES);
    cudaFuncSetAttribute(k_layer1, cudaFuncAttributeMaxDynamicSharedMemorySize, SMEM_BYTES);

    k_init<<<(B * T + 1023) / 1024, 1024>>>(x, B);

    const int nblk = B / BT;                    // 1024 CTAs
    for (int i = 0; i < NB; ++i) {
        k_layer0<<<nblk, NTH, SMEM_BYTES>>>(Whh0, Wih0, bih0, bhh0, i, B);
        k_gi1  <<<nblk, NTH, SMEM_BYTES>>>(Wih1, bih1, B);
        k_layer1<<<nblk, NTH, SMEM_BYTES>>>(Whh1, bhh1, Wlin, blin, out, i, B);
    }
}

// round 17
// speedup vs baseline: 3.4430x; 1.2842x over previous
#include <cuda_runtime.h>
#include <cuda_fp16.h>
#include <cstdint>

#define HID 100
#define T   10
#define NB  5
#define BT  64
#define NTH 1024
#define B_MAX 65536
#define NC_MAX (B_MAX / BT)

#define LDB 240            // fp16 row stride in bytes (120 elems)
#define GATE_ROWS 104      // padded W rows per gate block
#define KTILES 7           // k = 112 (100 real + 12 zero)

// SMEM byte layout
#define SM_W   0
#define W_BYTES (3 * GATE_ROWS * LDB)     // 74880
#define SM_H   74880       // 4 h buffers: [hi0, lo0, hi1, lo1], each 64*240
#define HBUF   15360
#define SM_AUX 136320      // 1024 floats aux
#define SMEM_BYTES 140416

// Scratch (static device memory; kernel_launch stays allocation-free)
__device__ float g_VBUF[(T + NB) * B_MAX];
// layer0 outputs, PRE-PACKED as the fp16 hi/lo ldsm tiles K2 consumes
__device__ __align__(16) char g_HB[(size_t)T * NC_MAX * 2 * HBUF];
// layer1 input gates, fragment-flat: [t][cta][slot 6][tid 1024] x float4
__device__ float g_GI1[(size_t)T * NC_MAX * 6 * NTH * 4];

__device__ __forceinline__ float sigf(float x)   { return __fdividef(1.f, 1.f + __expf(-x)); }
__device__ __forceinline__ float tanhf_(float x) { return 1.f - __fdividef(2.f, __expf(2.f * x) + 1.f); }

__device__ __forceinline__ uint32_t sm32(const void* p) {
    return (uint32_t)__cvta_generic_to_shared(p);
}

__device__ __forceinline__ void cp16c(char* smem_dst, const char* gsrc) {
    unsigned sa = (unsigned)__cvta_generic_to_shared(smem_dst);
    asm volatile("cp.async.ca.shared.global [%0], [%1], 16;" :: "r"(sa), "l"(gsrc));
}
#define CP_COMMIT() asm volatile("cp.async.commit_group;" ::: "memory")
#define CP_WAIT0()  asm volatile("cp.async.wait_group 0;" ::: "memory")

__device__ __forceinline__ void ldsm_x4(uint32_t* r, uint32_t a) {
    asm volatile("ldmatrix.sync.aligned.m8n8.x4.shared.b16 {%0,%1,%2,%3}, [%4];"
        : "=r"(r[0]), "=r"(r[1]), "=r"(r[2]), "=r"(r[3]) : "r"(a));
}
__device__ __forceinline__ void ldsm_x2(uint32_t* r, uint32_t a) {
    asm volatile("ldmatrix.sync.aligned.m8n8.x2.shared.b16 {%0,%1}, [%2];"
        : "=r"(r[0]), "=r"(r[1]) : "r"(a));
}
__device__ __forceinline__ void mma_f16(float* c, const uint32_t* a, const uint32_t* b) {
    asm volatile(
        "mma.sync.aligned.m16n8k16.row.col.f32.f16.f16.f32 "
        "{%0,%1,%2,%3}, {%4,%5,%6,%7}, {%8,%9}, {%0,%1,%2,%3};"
        : "+f"(c[0]), "+f"(c[1]), "+f"(c[2]), "+f"(c[3])
        : "r"(a[0]), "r"(a[1]), "r"(a[2]), "r"(a[3]), "r"(b[0]), "r"(b[1]));
}

__device__ __forceinline__ uint32_t pack_h2(float a, float b) {
    __half2 v = __halves2half2(__float2half_rn(a), __float2half_rn(b));
    return *reinterpret_cast<uint32_t*>(&v);
}
// pack fp32 pair into fp16 hi word + fp16 residual-lo word
__device__ __forceinline__ void pack_hilo(float a, float b, uint32_t& hi, uint32_t& lo) {
    __half ha = __float2half_rn(a), hb = __float2half_rn(b);
    hi = pack_h2(__half2float(ha), __half2float(hb));
    __half2 vh = *reinterpret_cast<__half2*>(&hi);
    lo = pack_h2(a - __half2float(vh.x), b - __half2float(vh.y));
}

// 32 warps = (4 mw) x (8 jw). Warp computes M-tile mt = mw (16 batches) x its
// j-slots: j0 = 16jw + 8d + 2(l&3), d < nd.
// acc[gate*2+d 6][c 4]; c: (b0,j0)(b0,j1)(b1,j0)(b1,j1), b0=16mw+l/4, b1=b0+8
// 2-term fp16: D = W_fp16 * h_hi + W_fp16 * h_lo  (W err 2^-11 dominates)
__device__ __forceinline__ void mma_all(uint32_t wsm,
                                        uint32_t hhi, uint32_t hlo,
                                        int jw, int mw, int l, int nd,
                                        float acc[6][4])
{
    #pragma unroll
    for (int j = 0; j < 6; ++j)
        #pragma unroll
        for (int k = 0; k < 4; ++k) acc[j][k] = 0.f;
    if (nd == 0) return;

    const uint32_t a_hi = hhi + (l & 15) * LDB + ((l >> 4) << 4) + mw * 16 * LDB;
    const uint32_t a_lo = hlo + (l & 15) * LDB + ((l >> 4) << 4) + mw * 16 * LDB;
    const uint32_t brow = (l & 7) * LDB + (((l >> 3) & 1) << 4);

    #pragma unroll
    for (int kt = 0; kt < KTILES; ++kt) {
        uint32_t ah[4], al[4];
        ldsm_x4(ah, a_hi + kt * 32);
        ldsm_x4(al, a_lo + kt * 32);
        #pragma unroll
        for (int g = 0; g < 3; ++g) {
            #pragma unroll
            for (int d = 0; d < 2; ++d) {
                if (d < nd) {
                    uint32_t off = (g * GATE_ROWS + 16 * jw + 8 * d) * LDB + kt * 32 + brow;
                    uint32_t bh[2];
                    ldsm_x2(bh, wsm + off);
                    mma_f16(acc[g * 2 + d], ah, bh);
                    mma_f16(acc[g * 2 + d], al, bh);
                }
            }
        }
    }
}

// W [300][100] fp32 -> smem fp16 tile [gate*104 + j][k], zero-padded
__device__ void setup_W(const float* __restrict__ W, char* smc, int tid)
{
    float4 z4 = make_float4(0.f, 0.f, 0.f, 0.f);
    for (int i = tid; i < W_BYTES / 16; i += NTH) ((float4*)(smc + SM_W))[i] = z4;
    for (int i = tid; i < 4 * HBUF / 16; i += NTH) ((float4*)(smc + SM_H))[i] = z4;
    __syncthreads();
    for (int idx = tid; idx < 3 * HID * HID; idx += NTH) {
        int g = idx / HID, k = idx - g * HID;
        int gate = g / HID, j = g - gate * HID;
        uint32_t off = (uint32_t)(gate * GATE_ROWS + j) * LDB + k * 2;
        *(__half*)(smc + SM_W + off) = __float2half_rn(W[idx]);
    }
}

// ---------------- init: VBUF[s][b] = x[b][s] ----------------
__global__ void k_init(const float* __restrict__ x, int B)
{
    int idx = blockIdx.x * blockDim.x + threadIdx.x;
    if (idx < B * T) {
        int b = idx / T, s = idx - b * T;
        g_VBUF[s * B + b] = x[idx];
    }
}

// ---------------- K1: layer-0 recurrence ----------------
__global__ void __launch_bounds__(NTH, 1)
k_layer0(const float* __restrict__ Whh0, const float* __restrict__ Wih0,
         const float* __restrict__ bih0, const float* __restrict__ bhh0,
         int iter, int B)
{
    extern __shared__ char smc[];
    float* aux = (float*)(smc + SM_AUX);   // [0:300) wih, [304:604) bih, [608:908) bhh
    const int tid = threadIdx.x, w = tid >> 5, l = tid & 31;
    const int mw = w & 3, jw = w >> 2;
    const int bg0 = blockIdx.x * BT;
    const int nd = (16 * jw < 100) ? ((16 * jw + 8 < 100) ? 2 : 1) : 0;
    const uint32_t wsm = sm32(smc + SM_W);

    setup_W(Whh0, smc, tid);
    for (int i = tid; i < 300; i += NTH) {
        aux[i] = Wih0[i]; aux[304 + i] = bih0[i]; aux[608 + i] = bhh0[i];
    }
    __syncthreads();

    float hold[2][4];
    #pragma unroll
    for (int b = 0; b < 2; ++b)
        #pragma unroll
        for (int c = 0; c < 4; ++c) hold[b][c] = 0.f;

    for (int t = 0; t < T; ++t) {
        char* hc = smc + SM_H + (t & 1) * 2 * HBUF;
        char* hn = smc + SM_H + ((t + 1) & 1) * 2 * HBUF;
        char* gb = g_HB + (size_t)(t * gridDim.x + blockIdx.x) * (2 * HBUF);
        float acc[6][4];
        mma_all(wsm, sm32(hc), sm32(hc + HBUF), jw, mw, l, nd, acc);

        const float* xr = g_VBUF + (size_t)(iter + t) * B + bg0;
        const int b0 = 16 * mw + (l >> 2), b1 = b0 + 8;
        const float x0 = xr[b0], x1 = xr[b1];
        #pragma unroll
        for (int d = 0; d < 2; ++d) {
            int j0 = 16 * jw + 8 * d + 2 * (l & 3);
            if (d < nd && j0 < 100) {
                float2 wr = *(float2*)(aux + j0),       wz = *(float2*)(aux + 100 + j0),       wn = *(float2*)(aux + 200 + j0);
                float2 br = *(float2*)(aux + 304 + j0), bz = *(float2*)(aux + 404 + j0),       bn = *(float2*)(aux + 504 + j0);
                float2 hr = *(float2*)(aux + 608 + j0), hz = *(float2*)(aux + 708 + j0),       hn2 = *(float2*)(aux + 808 + j0);
                float* ar = acc[0 + d]; float* az = acc[2 + d]; float* an = acc[4 + d];
                float h[4];
                #pragma unroll
                for (int c = 0; c < 4; ++c) {
                    float xv = (c < 2) ? x0 : x1;
                    float wrc = (c & 1) ? wr.y : wr.x, wzc = (c & 1) ? wz.y : wz.x, wnc = (c & 1) ? wn.y : wn.x;
                    float brc = (c & 1) ? br.y : br.x, bzc = (c & 1) ? bz.y : bz.x, bnc = (c & 1) ? bn.y : bn.x;
                    float hrc = (c & 1) ? hr.y : hr.x, hzc = (c & 1) ? hz.y : hz.x, hnc = (c & 1) ? hn2.y : hn2.x;
                    float r = sigf(xv * wrc + brc + ar[c] + hrc);
                    float z = sigf(xv * wzc + bzc + az[c] + hzc);
                    float n = tanhf_(xv * wnc + bnc + r * (an[c] + hnc));
                    h[c] = (1.f - z) * n + z * hold[d][c];
                    hold[d][c] = h[c];
                }
                uint32_t hi0, lo0, hi1, lo1;
                pack_hilo(h[0], h[1], hi0, lo0);
                pack_hilo(h[2], h[3], hi1, lo1);
                *(uint32_t*)(hn + b0 * LDB + j0 * 2)        = hi0;
                *(uint32_t*)(hn + HBUF + b0 * LDB + j0 * 2) = lo0;
                *(uint32_t*)(hn + b1 * LDB + j0 * 2)        = hi1;
                *(uint32_t*)(hn + HBUF + b1 * LDB + j0 * 2) = lo1;
                // pre-packed tile for K2 (same words)
                *(uint32_t*)(gb + b0 * LDB + j0 * 2)        = hi0;
                *(uint32_t*)(gb + HBUF + b0 * LDB + j0 * 2) = lo0;
                *(uint32_t*)(gb + b1 * LDB + j0 * 2)        = hi1;
                *(uint32_t*)(gb + HBUF + b1 * LDB + j0 * 2) = lo1;
            } else if (j0 < 112) {
                // zero-fill padded k region so K2's tiles stay exact
                *(uint32_t*)(gb + b0 * LDB + j0 * 2)        = 0u;
                *(uint32_t*)(gb + HBUF + b0 * LDB + j0 * 2) = 0u;
                *(uint32_t*)(gb + b1 * LDB + j0 * 2)        = 0u;
                *(uint32_t*)(gb + HBUF + b1 * LDB + j0 * 2) = 0u;
            }
        }
        __syncthreads();
    }
}

// ---------------- K2: GI1[t] = Wih1 * H1[t] + b_ih1 ----------------
__device__ __forceinline__ void stage_hb(char* dst, const char* src, int tid)
{
    for (int i = tid; i < 2 * HBUF / 16; i += NTH)
        cp16c(dst + i * 16, src + i * 16);
}

__global__ void __launch_bounds__(NTH, 1)
k_gi1(const float* __restrict__ Wih1, const float* __restrict__ bih1, int B)
{
    extern __shared__ char smc[];
    float* aux = (float*)(smc + SM_AUX);
    const int tid = threadIdx.x, w = tid >> 5, l = tid & 31;
    const int mw = w & 3, jw = w >> 2;
    const int nd = (16 * jw < 100) ? ((16 * jw + 8 < 100) ? 2 : 1) : 0;
    const uint32_t wsm = sm32(smc + SM_W);

    setup_W(Wih1, smc, tid);
    for (int i = tid; i < 300; i += NTH) aux[i] = bih1[i];

    stage_hb(smc + SM_H, g_HB + (size_t)blockIdx.x * (2 * HBUF), tid);
    CP_COMMIT();
    CP_WAIT0();
    __syncthreads();

    for (int t = 0; t < T; ++t) {
        char* hc = smc + SM_H + (t & 1) * 2 * HBUF;
        char* hn = smc + SM_H + ((t + 1) & 1) * 2 * HBUF;
        if (t + 1 < T) {
            stage_hb(hn, g_HB + (size_t)((t + 1) * gridDim.x + blockIdx.x) * (2 * HBUF), tid);
            CP_COMMIT();
        }

        float acc[6][4];
        mma_all(wsm, sm32(hc), sm32(hc + HBUF), jw, mw, l, nd, acc);

        if (nd > 0) {
            float* bt = g_GI1 + ((size_t)(t * gridDim.x + blockIdx.x) * 6 * NTH + tid) * 4;
            int j0b = 16 * jw + 2 * (l & 3);
            #pragma unroll
            for (int d = 0; d < 2; ++d) {
                int j0 = j0b + 8 * d;
                int js = (j0 < 100) ? j0 : 0;
                float2 br = *(float2*)(aux + js), bz = *(float2*)(aux + 100 + js), bn = *(float2*)(aux + 200 + js);
                #pragma unroll
                for (int g = 0; g < 3; ++g) {
                    float* a = acc[g * 2 + d];
                    float2 bs = (g == 0) ? br : ((g == 1) ? bz : bn);
                    int slot = d * 3 + g;
                    *(float4*)(bt + (size_t)slot * NTH * 4) =
                        make_float4(a[0] + bs.x, a[1] + bs.y, a[2] + bs.x, a[3] + bs.y);
                }
            }
        }
        CP_WAIT0();
        __syncthreads();
    }
}

// ---------------- K3: layer-1 recurrence + final linear ----------------
__global__ void __launch_bounds__(NTH, 1)
k_layer1(const float* __restrict__ Whh1, const float* __restrict__ bhh1,
         const float* __restrict__ Wlin, const float* __restrict__ blin,
         float* __restrict__ out, int iter, int B)
{
    extern __shared__ char smc[];
    float* aux = (float*)(smc + SM_AUX);   // [0:300) bhh, [304:404) wlin
    const int tid = threadIdx.x, w = tid >> 5, l = tid & 31;
    const int mw = w & 3, jw = w >> 2;
    const int bg0 = blockIdx.x * BT;
    const int nd = (16 * jw < 100) ? ((16 * jw + 8 < 100) ? 2 : 1) : 0;
    const uint32_t wsm = sm32(smc + SM_W);

    setup_W(Whh1, smc, tid);
    for (int i = tid; i < 300; i += NTH) aux[i] = bhh1[i];
    for (int i = tid; i < HID; i += NTH)  aux[304 + i] = Wlin[i];
    __syncthreads();

    float hold[2][4];
    #pragma unroll
    for (int b = 0; b < 2; ++b)
        #pragma unroll
        for (int c = 0; c < 4; ++c) hold[b][c] = 0.f;

    for (int t = 0; t < T; ++t) {
        char* hc = smc + SM_H + (t & 1) * 2 * HBUF;
        char* hn = smc + SM_H + ((t + 1) & 1) * 2 * HBUF;
        const float* bt = g_GI1 + ((size_t)(t * gridDim.x + blockIdx.x) * 6 * NTH + tid) * 4;

        float acc[6][4];
        mma_all(wsm, sm32(hc), sm32(hc + HBUF), jw, mw, l, nd, acc);

        const int b0 = 16 * mw + (l >> 2), b1 = b0 + 8;
        #pragma unroll
        for (int d = 0; d < 2; ++d) {
            if (d < nd) {
                float gi[12];
                #pragma unroll
                for (int g = 0; g < 3; ++g)
                    *(float4*)(gi + g * 4) = *(const float4*)(bt + (size_t)(d * 3 + g) * NTH * 4);

                int j0 = 16 * jw + 8 * d + 2 * (l & 3);
                bool jv = j0 < 100;
                int js = jv ? j0 : 0;
                float2 hr = *(float2*)(aux + js), hz = *(float2*)(aux + 100 + js), hn2 = *(float2*)(aux + 200 + js);
                float* ar = acc[0 + d]; float* az = acc[2 + d]; float* an = acc[4 + d];
                float h[4];
                #pragma unroll
                for (int c = 0; c < 4; ++c) {
                    float hrc = (c & 1) ? hr.y : hr.x, hzc = (c & 1) ? hz.y : hz.x, hnc = (c & 1) ? hn2.y : hn2.x;
                    float r = sigf(gi[0 + c] + ar[c] + hrc);
                    float z = sigf(gi[4 + c] + az[c] + hzc);
                    float n = tanhf_(gi[8 + c] + r * (an[c] + hnc));
                    h[c] = (1.f - z) * n + z * hold[d][c];
                    hold[d][c] = h[c];
                }
                if (jv) {
                    uint32_t hi0, lo0, hi1, lo1;
                    pack_hilo(h[0], h[1], hi0, lo0);
                    pack_hilo(h[2], h[3], hi1, lo1);
                    *(uint32_t*)(hn + b0 * LDB + j0 * 2)        = hi0;
                    *(uint32_t*)(hn + HBUF + b0 * LDB + j0 * 2) = lo0;
                    *(uint32_t*)(hn + b1 * LDB + j0 * 2)        = hi1;
                    *(uint32_t*)(hn + HBUF + b1 * LDB + j0 * 2) = lo1;
                }
            }
        }
        __syncthreads();
    }

    // dump fp32 h to scratch (reuse W region), reduce with W_lin
    float* scr = (float*)(smc + SM_W);   // [j][b], 100*64 floats
    {
        const int b0 = 16 * mw + (l >> 2), b1 = b0 + 8;
        #pragma unroll
        for (int d = 0; d < 2; ++d) {
            if (d < nd) {
                int j0 = 16 * jw + 8 * d + 2 * (l & 3);
                if (j0 < 100) {
                    scr[j0 * 64 + b0]       = hold[d][0];
                    scr[(j0 + 1) * 64 + b0] = hold[d][1];
                    scr[j0 * 64 + b1]       = hold[d][2];
                    scr[(j0 + 1) * 64 + b1] = hold[d][3];
                }
            }
        }
    }
    __syncthreads();
    if (tid < BT) {
        float acc = blin[0];
        #pragma unroll 10
        for (int k = 0; k < HID; ++k) acc += scr[k * 64 + tid] * aux[304 + k];
        g_VBUF[(size_t)(T + iter) * B + bg0 + tid] = acc;
        out[(bg0 + tid) * NB + iter] = acc;
    }
}

extern "C" void kernel_launch(void* const* d_in, const int* in_sizes, int n_in,
                              void* d_out, int out_size)
{
    const float* x    = (const float*)d_in[0];
    const float* Wih0 = (const float*)d_in[1];
    const float* Whh0 = (const float*)d_in[2];
    const float* bih0 = (const float*)d_in[3];
    const float* bhh0 = (const float*)d_in[4];
    const float* Wih1 = (const float*)d_in[5];
    const float* Whh1 = (const float*)d_in[6];
    const float* bih1 = (const float*)d_in[7];
    const float* bhh1 = (const float*)d_in[8];
    const float* Wlin = (const float*)d_in[9];
    const float* blin = (const float*)d_in[10];
    float* out = (float*)d_out;

    const int B = in_sizes[0] / T;              // 65536

    cudaFuncSetAttribute(k_layer0, cudaFuncAttributeMaxDynamicSharedMemorySize, SMEM_BYTES);
    cudaFuncSetAttribute(k_gi1,    cudaFuncAttributeMaxDynamicSharedMemorySize, SMEM_BYTES);
    cudaFuncSetAttribute(k_layer1, cudaFuncAttributeMaxDynamicSharedMemorySize, SMEM_BYTES);

    k_init<<<(B * T + 1023) / 1024, 1024>>>(x, B);

    const int nblk = B / BT;                    // 1024 CTAs
    for (int i = 0; i < NB; ++i) {
        k_layer0<<<nblk, NTH, SMEM_BYTES>>>(Whh0, Wih0, bih0, bhh0, i, B);
        k_gi1  <<<nblk, NTH, SMEM_BYTES>>>(Wih1, bih1, B);
        k_layer1<<<nblk, NTH, SMEM_BYTES>>>(Whh1, bhh1, Wlin, blin, out, i, B);
    }
}